// round 9
// baseline (speedup 1.0000x reference)
#include <cuda_runtime.h>
#include <cuda_bf16.h>
#include <cstdint>
#include <math.h>

#define BB 4
#define SS 2048
#define DD 1024

// ---------------------------------------------------------------------------
// Scratch (device globals — allocation-free per harness rules)
// bf16 operand buffers use [hi | lo] row layout: row length = 2*Kphys.
// lo is UNSCALED (bf16 exponent range = fp32), so all three split products
// accumulate directly into one fp32 accumulator.
// ---------------------------------------------------------------------------
__device__ __nv_bfloat16 g_x3 [(size_t)BB * SS * 2 * DD];   // x split      [8192][2048]
__device__ __nv_bfloat16 g_wqt[(size_t)DD * 2 * DD];        // Wq^T split   [1024][2048]
__device__ __nv_bfloat16 g_wkt[(size_t)DD * 2 * DD];
__device__ __nv_bfloat16 g_wvt[(size_t)DD * 2 * DD];
__device__ __nv_bfloat16 g_q3 [(size_t)BB * SS * 2 * DD];   // q split
__device__ __nv_bfloat16 g_k3 [(size_t)BB * SS * 2 * DD];   // k split
__device__ float         g_vf [(size_t)BB * SS * DD];       // v fp32
__device__ __nv_bfloat16 g_vt3[(size_t)BB * DD * 2 * SS];   // v^T split  [b][1024][4096]
__device__ float         g_s  [(size_t)BB * SS * SS];       // raw scores fp32
__device__ __nv_bfloat16 g_a3 [(size_t)BB * SS * 2 * SS];   // attn split [b][2048][4096]

// ---------------------------------------------------------------------------
// PTX helpers (compute_103-safe: cp.async, ldmatrix, mma.sync only)
// ---------------------------------------------------------------------------
__device__ __forceinline__ void cp16(uint32_t dst, const void* src) {
    asm volatile("cp.async.cg.shared.global [%0], [%1], 16;\n" :: "r"(dst), "l"(src));
}
__device__ __forceinline__ uint32_t swz128(uint32_t off) { return off ^ ((off >> 3) & 0x70); }

__device__ __forceinline__ void ldsm4(uint32_t& r0, uint32_t& r1, uint32_t& r2, uint32_t& r3,
                                      uint32_t addr) {
    asm volatile("ldmatrix.sync.aligned.m8n8.x4.shared.b16 {%0,%1,%2,%3}, [%4];"
                 : "=r"(r0), "=r"(r1), "=r"(r2), "=r"(r3) : "r"(addr));
}

__device__ __forceinline__ void mma_bf16(float c[4], const uint32_t a[4], const uint32_t b0,
                                         const uint32_t b1) {
    asm volatile(
        "mma.sync.aligned.m16n8k16.row.col.f32.bf16.bf16.f32 "
        "{%0,%1,%2,%3}, {%4,%5,%6,%7}, {%8,%9}, {%0,%1,%2,%3};\n"
        : "+f"(c[0]), "+f"(c[1]), "+f"(c[2]), "+f"(c[3])
        : "r"(a[0]), "r"(a[1]), "r"(a[2]), "r"(a[3]), "r"(b0), "r"(b1));
}

// ---------------------------------------------------------------------------
// Fused-pass mma.sync GEMM. CTA tile 128x128, logical BK=32 per chunk.
// Each 128B SMEM row packs [hi 64B | lo 64B] of the SAME 32 k-columns:
//   acc += Ah*Bh + Ah*Bl + Al*Bh        (Al*Bl dropped, ~2^-16 relative)
// 256 threads = 8 warps of 64x32 (2m x 4n) -> 64 acc regs/thread; target
// <=128 regs so 2 CTAs/SM = 16 warps/SM (vs 8 in the 64x64 variant).
// 3-stage cp.async pipeline.
// sched 1: fused QKV (w = t>>9 selects Wq/Wk/Wv; q/k epilogue emits split bf16)
// sched 2: scores QK^T, triangular causal tile list (136 tiles per batch)
// sched 3: attn @ V, K clamped at diagonal block, longest tiles first
// ---------------------------------------------------------------------------
#define NSTAGE 3
#define STAGE_BYTES 32768            // A 16KB + B 16KB
#define GEMM_SMEM (NSTAGE * STAGE_BYTES)

__global__ __launch_bounds__(256, 2)
void gemm_mma(int sched,
              const __nv_bfloat16* __restrict__ A,
              const __nv_bfloat16* __restrict__ B0,
              const __nv_bfloat16* __restrict__ B1,
              const __nv_bfloat16* __restrict__ B2,
              void* __restrict__ C0, void* __restrict__ C1, void* __restrict__ C2)
{
    extern __shared__ __align__(1024) char smem[];
    const uint32_t base0 = (uint32_t)__cvta_generic_to_shared(smem);

    const int tid  = threadIdx.x;
    const int wid  = tid >> 5;
    const int lane = tid & 31;
    const int wm   = wid >> 2;      // 0..1  (m)
    const int wn   = wid & 3;       // 0..3  (n)

    // ---- decode tile ----
    const int t = blockIdx.x;
    const __nv_bfloat16 *Ag, *Bg;
    void* Cv;
    int m0, n0, N_C, rowL, nC, mode, P;
    if (sched == 1) {                       // fused QKV
        const int w = t >> 9;
        const int r = t & 511;
        m0 = (r >> 3) * 128; n0 = (r & 7) * 128;
        Ag = A;
        Bg = (w == 0) ? B0 : ((w == 1) ? B1 : B2);
        Cv = (w == 0) ? C0 : ((w == 1) ? C1 : C2);
        mode = (w == 2) ? 0 : 1;
        N_C = DD; rowL = 2 * DD; nC = DD / 32; P = DD;
    } else if (sched == 2) {                // scores, triangular decode
        const int z  = t / 136;
        const int tt = t - z * 136;
        int r = (int)floorf((sqrtf(8.0f * tt + 1.0f) - 1.0f) * 0.5f);
        while ((r + 1) * (r + 2) / 2 <= tt) r++;
        while (r * (r + 1) / 2 > tt) r--;
        const int c = tt - r * (r + 1) / 2;
        m0 = r * 128; n0 = c * 128;
        Ag = A  + (size_t)z * SS * 2 * DD;
        Bg = B0 + (size_t)z * SS * 2 * DD;
        Cv = (float*)C0 + (size_t)z * SS * SS;
        mode = 0; N_C = SS; rowL = 2 * DD; nC = DD / 32; P = DD;
    } else {                                // attn @ V, longest-first
        const int m    = 15 - (t >> 5);
        const int rest = t & 31;
        m0 = m * 128; n0 = (rest & 7) * 128;
        const int z = rest >> 3;
        Ag = A  + (size_t)z * SS * 2 * SS;
        Bg = B0 + (size_t)z * DD * 2 * SS;
        Cv = (float*)C0 + (size_t)z * SS * DD;
        mode = 0; N_C = DD; rowL = 2 * SS;
        nC = min(SS / 32, 4 * m + 4); P = SS;
    }

    // ldmatrix base offsets (row*128 + 16B column pick), swizzle applied per use
    const int mo  = ((lane >> 3) & 1) * 8 + (lane & 7);
    const int akb = ((lane >> 4) & 1) * 16;
    const int no  = ((lane >> 4) & 1) * 8 + (lane & 7);
    const int bkb = ((lane >> 3) & 1) * 16;
    uint32_t aO[4], bO[2];
    #pragma unroll
    for (int f = 0; f < 4; f++) aO[f] = (uint32_t)((wm * 64 + f * 16 + mo) * 128 + akb);
    #pragma unroll
    for (int f = 0; f < 2; f++) bO[f] = (uint32_t)((wn * 32 + f * 16 + no) * 128 + bkb);

    float acc[4][4][4];
    #pragma unroll
    for (int i = 0; i < 4; i++)
        #pragma unroll
        for (int j = 0; j < 4; j++)
            #pragma unroll
            for (int q = 0; q < 4; q++) acc[i][j][q] = 0.0f;

    // chunk loader: 256 threads; thread t<128 loads A row t, else B row t-128.
    // Row = [hi 64B | lo 64B] of the same 32 k-columns (8 cp16 per thread).
    auto load_chunk = [&](int c) {
        const int st = c % NSTAGE;
        const int row = tid & 127;
        const int isB = tid >> 7;
        const __nv_bfloat16* src = (isB ? (Bg + (size_t)(n0 + row) * rowL)
                                        : (Ag + (size_t)(m0 + row) * rowL)) + c * 32;
        const uint32_t dBase = base0 + st * STAGE_BYTES + isB * 16384;
        const uint32_t ro = (uint32_t)row * 128;
        #pragma unroll
        for (int s4 = 0; s4 < 4; s4++) {
            cp16(dBase + swz128(ro + s4 * 16),      src + s4 * 8);
            cp16(dBase + swz128(ro + 64 + s4 * 16), src + P + s4 * 8);
        }
        asm volatile("cp.async.commit_group;\n");
    };

    load_chunk(0);
    if (nC > 1) load_chunk(1);

    for (int c = 0; c < nC; ++c) {
        if (c + 1 < nC) asm volatile("cp.async.wait_group 1;\n" ::: "memory");
        else            asm volatile("cp.async.wait_group 0;\n" ::: "memory");
        __syncthreads();

        if (c + 2 < nC) load_chunk(c + 2);

        const uint32_t aB = base0 + (c % NSTAGE) * STAGE_BYTES;
        const uint32_t bB = aB + 16384;

        #pragma unroll
        for (int ks = 0; ks < 2; ks++) {
            const uint32_t kso = (uint32_t)(ks * 32);
            uint32_t ah[4][4], bh[2][4];
            #pragma unroll
            for (int f = 0; f < 4; f++)
                ldsm4(ah[f][0], ah[f][1], ah[f][2], ah[f][3], aB + swz128(aO[f] + kso));
            #pragma unroll
            for (int f = 0; f < 2; f++)
                ldsm4(bh[f][0], bh[f][1], bh[f][2], bh[f][3], bB + swz128(bO[f] + kso));
            {
                uint32_t al[4][4];
                #pragma unroll
                for (int f = 0; f < 4; f++)
                    ldsm4(al[f][0], al[f][1], al[f][2], al[f][3],
                          aB + swz128(aO[f] + kso + 64));
                // pass 1: Ah * Bh
                #pragma unroll
                for (int im = 0; im < 4; im++)
                    #pragma unroll
                    for (int jn = 0; jn < 4; jn++)
                        mma_bf16(acc[im][jn], ah[im],
                                 bh[jn >> 1][(jn & 1) * 2], bh[jn >> 1][(jn & 1) * 2 + 1]);
                // pass 2: Al * Bh
                #pragma unroll
                for (int im = 0; im < 4; im++)
                    #pragma unroll
                    for (int jn = 0; jn < 4; jn++)
                        mma_bf16(acc[im][jn], al[im],
                                 bh[jn >> 1][(jn & 1) * 2], bh[jn >> 1][(jn & 1) * 2 + 1]);
            }
            {
                uint32_t bl[2][4];
                #pragma unroll
                for (int f = 0; f < 2; f++)
                    ldsm4(bl[f][0], bl[f][1], bl[f][2], bl[f][3],
                          bB + swz128(bO[f] + kso + 64));
                // pass 3: Ah * Bl
                #pragma unroll
                for (int im = 0; im < 4; im++)
                    #pragma unroll
                    for (int jn = 0; jn < 4; jn++)
                        mma_bf16(acc[im][jn], ah[im],
                                 bl[jn >> 1][(jn & 1) * 2], bl[jn >> 1][(jn & 1) * 2 + 1]);
            }
        }
    }

    // ---- epilogue ----
    #pragma unroll
    for (int im = 0; im < 4; im++) {
        const int r = m0 + wm * 64 + im * 16 + (lane >> 2);
        #pragma unroll
        for (int jn = 0; jn < 4; jn++) {
            const int cc = n0 + wn * 32 + jn * 8 + (lane & 3) * 2;
            if (mode == 0) {
                float* Cg = (float*)Cv;
                *(float2*)(Cg + (size_t)r * N_C + cc)       = make_float2(acc[im][jn][0], acc[im][jn][1]);
                *(float2*)(Cg + (size_t)(r + 8) * N_C + cc) = make_float2(acc[im][jn][2], acc[im][jn][3]);
            } else {
                __nv_bfloat16* Cg = (__nv_bfloat16*)Cv;
                #pragma unroll
                for (int hr = 0; hr < 2; hr++) {
                    const float v0 = acc[im][jn][hr * 2];
                    const float v1 = acc[im][jn][hr * 2 + 1];
                    const __nv_bfloat16 h0 = __float2bfloat16(v0);
                    const __nv_bfloat16 l0 = __float2bfloat16(v0 - __bfloat162float(h0));
                    const __nv_bfloat16 h1 = __float2bfloat16(v1);
                    const __nv_bfloat16 l1 = __float2bfloat16(v1 - __bfloat162float(h1));
                    __nv_bfloat16* row = Cg + (size_t)(r + hr * 8) * (2 * N_C);
                    *(__nv_bfloat162*)(row + cc)       = __halves2bfloat162(h0, h1);
                    *(__nv_bfloat162*)(row + N_C + cc) = __halves2bfloat162(l0, l1);
                }
            }
        }
    }
}

// ---------------------------------------------------------------------------
// fp32 -> [hi | lo] bf16 split, same row layout (row len 2K).
// ---------------------------------------------------------------------------
__global__ __launch_bounds__(256)
void conv_split2(const float* __restrict__ src, __nv_bfloat16* __restrict__ dst, int K)
{
    const long long idx = (long long)blockIdx.x * 256 + threadIdx.x;
    const long long m = idx / K;
    const int j = (int)(idx % K);
    const float v = src[idx];
    const __nv_bfloat16 h = __float2bfloat16(v);
    const __nv_bfloat16 l = __float2bfloat16(v - __bfloat162float(h));
    __nv_bfloat16* o = dst + m * 2LL * K;
    o[j] = h; o[K + j] = l;
}

// ---------------------------------------------------------------------------
// Merged weight transpose: fp32 [D][D] -> split bf16 [D][2D], 3 weights via z.
// ---------------------------------------------------------------------------
__global__ __launch_bounds__(256)
void transposeW(const float* __restrict__ s0, const float* __restrict__ s1,
                const float* __restrict__ s2,
                __nv_bfloat16* __restrict__ d0, __nv_bfloat16* __restrict__ d1,
                __nv_bfloat16* __restrict__ d2)
{
    __shared__ float tile[32][33];
    const int z = blockIdx.z;
    const float* src = (z == 0) ? s0 : ((z == 1) ? s1 : s2);
    __nv_bfloat16* dst = (z == 0) ? d0 : ((z == 1) ? d1 : d2);
    const int r0 = blockIdx.y * 32, c0 = blockIdx.x * 32;
    const int tx = threadIdx.x & 31;
    const int ty = threadIdx.x >> 5;

    #pragma unroll
    for (int dy = 0; dy < 32; dy += 8)
        tile[ty + dy][tx] = src[(size_t)(r0 + ty + dy) * DD + c0 + tx];
    __syncthreads();

    #pragma unroll
    for (int dy = 0; dy < 32; dy += 8) {
        const int c = c0 + ty + dy;
        const int r = r0 + tx;
        const float v = tile[tx][ty + dy];
        const __nv_bfloat16 h = __float2bfloat16(v);
        const __nv_bfloat16 l = __float2bfloat16(v - __bfloat162float(h));
        __nv_bfloat16* o = dst + (size_t)c * 2 * DD;
        o[r] = h; o[DD + r] = l;
    }
}

// ---------------------------------------------------------------------------
// v transpose: fp32 [S][D] per batch -> split bf16 [D][2S]
// ---------------------------------------------------------------------------
__global__ __launch_bounds__(256)
void transposeV(const float* __restrict__ src, __nv_bfloat16* __restrict__ dst)
{
    __shared__ float tile[32][33];
    src += (size_t)blockIdx.z * SS * DD;
    dst += (size_t)blockIdx.z * DD * 2 * SS;
    const int r0 = blockIdx.y * 32, c0 = blockIdx.x * 32;
    const int tx = threadIdx.x & 31;
    const int ty = threadIdx.x >> 5;

    #pragma unroll
    for (int dy = 0; dy < 32; dy += 8)
        tile[ty + dy][tx] = src[(size_t)(r0 + ty + dy) * DD + c0 + tx];
    __syncthreads();

    #pragma unroll
    for (int dy = 0; dy < 32; dy += 8) {
        const int c = c0 + ty + dy;
        const int r = r0 + tx;
        const float v = tile[tx][ty + dy];
        const __nv_bfloat16 h = __float2bfloat16(v);
        const __nv_bfloat16 l = __float2bfloat16(v - __bfloat162float(h));
        __nv_bfloat16* o = dst + (size_t)c * 2 * SS;
        o[r] = h; o[SS + r] = l;
    }
}

// ---------------------------------------------------------------------------
// Causal softmax emitting split bf16 attn [hi | lo]. Zero-fills only up to the
// 128-row diagonal-block boundary (AV K-clamp never reads past it).
// ---------------------------------------------------------------------------
__global__ __launch_bounds__(256)
void softmax2(const float* __restrict__ Sc, __nv_bfloat16* __restrict__ A3,
              int S, float scale)
{
    const long long row = blockIdx.x;            // b*S + i
    const int i = (int)(row % S);
    const float* p = Sc + row * (long long)S;
    __nv_bfloat16* out = A3 + row * (long long)(2 * S);
    const int L = i + 1;
    const int Lz = ((i >> 7) + 1) << 7;          // diagonal-block end

    const int tid  = threadIdx.x;
    const int lane = tid & 31;
    const int wid  = tid >> 5;
    __shared__ float red[32];

    float mx = -INFINITY;
    for (int j = tid; j < L; j += 256) mx = fmaxf(mx, p[j]);
    #pragma unroll
    for (int o = 16; o; o >>= 1) mx = fmaxf(mx, __shfl_xor_sync(0xffffffffu, mx, o));
    if (lane == 0) red[wid] = mx;
    __syncthreads();
    if (tid == 0) {
        float m = red[0];
        #pragma unroll
        for (int w = 1; w < 8; w++) m = fmaxf(m, red[w]);
        red[0] = m;
    }
    __syncthreads();
    mx = red[0];
    __syncthreads();

    float e[8];
    float sum = 0.0f;
    int cnt = 0;
    for (int j = tid; j < L; j += 256) {
        const float ev = __expf((p[j] - mx) * scale);
        e[cnt++] = ev;
        sum += ev;
    }
    #pragma unroll
    for (int o = 16; o; o >>= 1) sum += __shfl_xor_sync(0xffffffffu, sum, o);
    if (lane == 0) red[wid] = sum;
    __syncthreads();
    if (tid == 0) {
        float s = red[0];
        #pragma unroll
        for (int w = 1; w < 8; w++) s += red[w];
        red[0] = s;
    }
    __syncthreads();
    const float inv = 1.0f / red[0];

    cnt = 0;
    for (int j = tid; j < L; j += 256) {
        const float v = e[cnt++] * inv;
        const __nv_bfloat16 h = __float2bfloat16(v);
        const __nv_bfloat16 l = __float2bfloat16(v - __bfloat162float(h));
        out[j] = h; out[S + j] = l;
    }
    const __nv_bfloat16 zero = __float2bfloat16(0.0f);
    for (int j = L + tid; j < Lz; j += 256) {
        out[j] = zero; out[S + j] = zero;
    }
}

// ---------------------------------------------------------------------------
extern "C" void kernel_launch(void* const* d_in, const int* in_sizes, int n_in,
                              void* d_out, int out_size)
{
    (void)in_sizes; (void)n_in; (void)out_size;
    const float* x  = (const float*)d_in[0];
    const float* Wq = (const float*)d_in[1];
    const float* Wk = (const float*)d_in[2];
    const float* Wv = (const float*)d_in[3];
    float* out = (float*)d_out;

    __nv_bfloat16 *x3, *wqt, *wkt, *wvt, *q3, *k3, *vt3, *a3;
    float *vf, *s;
    cudaGetSymbolAddress((void**)&x3,  g_x3);
    cudaGetSymbolAddress((void**)&wqt, g_wqt);
    cudaGetSymbolAddress((void**)&wkt, g_wkt);
    cudaGetSymbolAddress((void**)&wvt, g_wvt);
    cudaGetSymbolAddress((void**)&q3,  g_q3);
    cudaGetSymbolAddress((void**)&k3,  g_k3);
    cudaGetSymbolAddress((void**)&vf,  g_vf);
    cudaGetSymbolAddress((void**)&vt3, g_vt3);
    cudaGetSymbolAddress((void**)&s,   g_s);
    cudaGetSymbolAddress((void**)&a3,  g_a3);

    cudaFuncSetAttribute(gemm_mma, cudaFuncAttributeMaxDynamicSharedMemorySize, GEMM_SMEM);

    const int B = BB, S = SS, D = DD;
    const long long MS = (long long)B * S;   // 8192

    // launch 0: x conversion
    conv_split2<<<(int)(MS * D / 256), 256>>>(x, x3, D);

    // launch 1: merged weight transposes
    {
        dim3 tg(D / 32, D / 32, 3);
        transposeW<<<tg, 256>>>(Wq, Wk, Wv, wqt, wkt, wvt);
    }

    // launch 2: fused QKV projections (1536 tiles)
    gemm_mma<<<1536, 256, GEMM_SMEM>>>(1, x3, wqt, wkt, wvt, q3, k3, vf);

    // launch 3 (ncu-captured): scores = Q K^T, triangular tile list
    gemm_mma<<<136 * B, 256, GEMM_SMEM>>>(2, q3, k3, nullptr, nullptr,
                                          s, nullptr, nullptr);

    // launch 4: v transpose-split
    {
        dim3 tg(D / 32, S / 32, B);
        transposeV<<<tg, 256>>>(vf, vt3);
    }

    // launch 5: softmax -> split bf16 attn
    softmax2<<<B * S, 256>>>(s, a3, S, 0.03125f);

    // launch 6: out = attn @ V (K-clamped, longest tiles first)
    gemm_mma<<<16 * 8 * B, 256, GEMM_SMEM>>>(3, a3, vt3, nullptr, nullptr,
                                             out, nullptr, nullptr);
}

// round 10
// speedup vs baseline: 1.0317x; 1.0317x over previous
#include <cuda_runtime.h>
#include <cuda_bf16.h>
#include <cstdint>
#include <math.h>

#define BB 4
#define SS 2048
#define DD 1024

// ---------------------------------------------------------------------------
// Scratch (device globals — allocation-free per harness rules)
// bf16 operand buffers use [hi | lo] row layout: row length = 2*Kphys.
// lo is UNSCALED (bf16 exponent range = fp32), so all three split products
// accumulate directly into one fp32 accumulator.
// ---------------------------------------------------------------------------
__device__ __nv_bfloat16 g_x3 [(size_t)BB * SS * 2 * DD];   // x split      [8192][2048]
__device__ __nv_bfloat16 g_wqt[(size_t)DD * 2 * DD];        // Wq^T split   [1024][2048]
__device__ __nv_bfloat16 g_wkt[(size_t)DD * 2 * DD];
__device__ __nv_bfloat16 g_wvt[(size_t)DD * 2 * DD];
__device__ __nv_bfloat16 g_q3 [(size_t)BB * SS * 2 * DD];   // q split
__device__ __nv_bfloat16 g_k3 [(size_t)BB * SS * 2 * DD];   // k split
__device__ __nv_bfloat16 g_vt3[(size_t)BB * DD * 2 * SS];   // v^T split  [b][1024][4096]
__device__ float         g_s  [(size_t)BB * SS * SS];       // raw scores fp32
__device__ __nv_bfloat16 g_a3 [(size_t)BB * SS * 2 * SS];   // attn split [b][2048][4096]

// ---------------------------------------------------------------------------
// PTX helpers (compute_103-safe: cp.async, ldmatrix, mma.sync only)
// ---------------------------------------------------------------------------
__device__ __forceinline__ void cp16(uint32_t dst, const void* src) {
    asm volatile("cp.async.cg.shared.global [%0], [%1], 16;\n" :: "r"(dst), "l"(src));
}
__device__ __forceinline__ uint32_t swz128(uint32_t off) { return off ^ ((off >> 3) & 0x70); }

__device__ __forceinline__ void ldsm4(uint32_t& r0, uint32_t& r1, uint32_t& r2, uint32_t& r3,
                                      uint32_t addr) {
    asm volatile("ldmatrix.sync.aligned.m8n8.x4.shared.b16 {%0,%1,%2,%3}, [%4];"
                 : "=r"(r0), "=r"(r1), "=r"(r2), "=r"(r3) : "r"(addr));
}

__device__ __forceinline__ void mma_bf16(float c[4], const uint32_t a[4], const uint32_t b0,
                                         const uint32_t b1) {
    asm volatile(
        "mma.sync.aligned.m16n8k16.row.col.f32.bf16.bf16.f32 "
        "{%0,%1,%2,%3}, {%4,%5,%6,%7}, {%8,%9}, {%0,%1,%2,%3};\n"
        : "+f"(c[0]), "+f"(c[1]), "+f"(c[2]), "+f"(c[3])
        : "r"(a[0]), "r"(a[1]), "r"(a[2]), "r"(a[3]), "r"(b0), "r"(b1));
}

// ---------------------------------------------------------------------------
// BIG kernel: CTA tile 128x256, 256 threads = 8 warps of 64x64 (2m x 4n).
// Fused-pass chunks: 128B SMEM row = [hi 64B | lo 64B] of the same 32 k-cols:
//   acc += Ah*Bh + Ah*Bl + Al*Bh     (Al*Bl dropped, ~2^-16 relative)
// 3-stage cp.async (48KB/stage), 1 CTA/SM.
// sched 1: fused QKV (w selects Wq/Wk/Wv). q/k epilogue emits split bf16;
//          v epilogue transposes through SMEM and writes v^T split directly.
// sched 2: scores QK^T, triangular list on 128x256 tiles (72 per batch).
// ---------------------------------------------------------------------------
#define BIG_STAGE 49152              // A 16KB + B 32KB
#define BIG_SMEM (3 * BIG_STAGE)     // 147456

__global__ __launch_bounds__(256, 1)
void gemm_big(int sched,
              const __nv_bfloat16* __restrict__ A,
              const __nv_bfloat16* __restrict__ B0,
              const __nv_bfloat16* __restrict__ B1,
              const __nv_bfloat16* __restrict__ B2,
              void* __restrict__ C0, void* __restrict__ C1,
              __nv_bfloat16* __restrict__ Cvt)
{
    extern __shared__ __align__(1024) char smem[];
    const uint32_t base0 = (uint32_t)__cvta_generic_to_shared(smem);

    const int tid  = threadIdx.x;
    const int wid  = tid >> 5;
    const int lane = tid & 31;
    const int wm   = wid >> 2;      // 0..1
    const int wn   = wid & 3;       // 0..3

    // ---- decode tile ----
    const int t = blockIdx.x;
    const __nv_bfloat16 *Ag, *Bg;
    void* Cv = nullptr;
    int m0, n0, N_C, mode;
    const int rowL = 2 * DD, nC = DD / 32, P = DD;
    if (sched == 1) {                       // fused QKV
        const int m  = t / 12;
        const int nn = t - m * 12;
        const int w  = nn >> 2;
        m0 = m * 128; n0 = (nn & 3) * 256;
        Ag = A;
        Bg = (w == 0) ? B0 : ((w == 1) ? B1 : B2);
        if (w == 0) { Cv = C0; mode = 1; }
        else if (w == 1) { Cv = C1; mode = 1; }
        else { mode = 2; }
        N_C = DD;
    } else {                                // scores, triangular decode (72/batch)
        const int z  = t / 72;
        const int tt = t - z * 72;
        int r = 0, off = 0, col = 0;
        for (;; r++) {
            const int cnt = (r >> 1) + 1;
            if (off + cnt > tt) { col = tt - off; break; }
            off += cnt;
        }
        m0 = r * 128; n0 = col * 256;
        Ag = A  + (size_t)z * SS * 2 * DD;
        Bg = B0 + (size_t)z * SS * 2 * DD;
        Cv = (float*)C0 + (size_t)z * SS * SS;
        mode = 0; N_C = SS;
    }

    // ldmatrix base offsets (rows of 128B, SW128 swizzle applied per use)
    const int mo  = ((lane >> 3) & 1) * 8 + (lane & 7);
    const int akb = ((lane >> 4) & 1) * 16;
    const int no  = ((lane >> 4) & 1) * 8 + (lane & 7);
    const int bkb = ((lane >> 3) & 1) * 16;
    uint32_t aO[4], bO[4];
    #pragma unroll
    for (int f = 0; f < 4; f++) {
        aO[f] = (uint32_t)((wm * 64 + f * 16 + mo) * 128 + akb);
        bO[f] = (uint32_t)((wn * 64 + f * 16 + no) * 128 + bkb);
    }

    float acc[4][8][4];
    #pragma unroll
    for (int i = 0; i < 4; i++)
        #pragma unroll
        for (int j = 0; j < 8; j++)
            #pragma unroll
            for (int q = 0; q < 4; q++) acc[i][j][q] = 0.0f;

    // chunk loader: A rows 0..127 + B rows 0..255 (each 128B = [hi|lo] 32k).
    // thread t: row t (A if t<128 else B row t-128); t<128 also B row t+128.
    auto load_chunk = [&](int c) {
        const int st = c % 3;
        const uint32_t aBase = base0 + st * BIG_STAGE;
        const uint32_t bBase = aBase + 16384;
        {
            const int isB = tid >> 7;
            const int row = tid & 127;
            const __nv_bfloat16* src = (isB ? (Bg + (size_t)(n0 + row) * rowL)
                                            : (Ag + (size_t)(m0 + row) * rowL)) + c * 32;
            const uint32_t d = (isB ? bBase : aBase);
            const uint32_t ro = (uint32_t)row * 128;
            #pragma unroll
            for (int s4 = 0; s4 < 4; s4++) {
                cp16(d + swz128(ro + s4 * 16),      src + s4 * 8);
                cp16(d + swz128(ro + 64 + s4 * 16), src + P + s4 * 8);
            }
        }
        if (tid < 128) {
            const int row = tid + 128;
            const __nv_bfloat16* src = Bg + (size_t)(n0 + row) * rowL + c * 32;
            const uint32_t ro = (uint32_t)row * 128;
            #pragma unroll
            for (int s4 = 0; s4 < 4; s4++) {
                cp16(bBase + swz128(ro + s4 * 16),      src + s4 * 8);
                cp16(bBase + swz128(ro + 64 + s4 * 16), src + P + s4 * 8);
            }
        }
        asm volatile("cp.async.commit_group;\n");
    };

    load_chunk(0);
    load_chunk(1);

    for (int c = 0; c < nC; ++c) {
        if (c + 1 < nC) asm volatile("cp.async.wait_group 1;\n" ::: "memory");
        else            asm volatile("cp.async.wait_group 0;\n" ::: "memory");
        __syncthreads();

        if (c + 2 < nC) load_chunk(c + 2);

        const uint32_t aB = base0 + (c % 3) * BIG_STAGE;
        const uint32_t bB = aB + 16384;

        #pragma unroll
        for (int ks = 0; ks < 2; ks++) {
            const uint32_t kso = (uint32_t)(ks * 32);
            uint32_t ah[4][4], bh[4][4];
            #pragma unroll
            for (int f = 0; f < 4; f++)
                ldsm4(ah[f][0], ah[f][1], ah[f][2], ah[f][3], aB + swz128(aO[f] + kso));
            #pragma unroll
            for (int f = 0; f < 4; f++)
                ldsm4(bh[f][0], bh[f][1], bh[f][2], bh[f][3], bB + swz128(bO[f] + kso));
            {
                uint32_t al[4][4];
                #pragma unroll
                for (int f = 0; f < 4; f++)
                    ldsm4(al[f][0], al[f][1], al[f][2], al[f][3],
                          aB + swz128(aO[f] + kso + 64));
                #pragma unroll
                for (int im = 0; im < 4; im++)
                    #pragma unroll
                    for (int jn = 0; jn < 8; jn++)
                        mma_bf16(acc[im][jn], ah[im],
                                 bh[jn >> 1][(jn & 1) * 2], bh[jn >> 1][(jn & 1) * 2 + 1]);
                #pragma unroll
                for (int im = 0; im < 4; im++)
                    #pragma unroll
                    for (int jn = 0; jn < 8; jn++)
                        mma_bf16(acc[im][jn], al[im],
                                 bh[jn >> 1][(jn & 1) * 2], bh[jn >> 1][(jn & 1) * 2 + 1]);
            }
            {
                uint32_t bl[4][4];
                #pragma unroll
                for (int f = 0; f < 4; f++)
                    ldsm4(bl[f][0], bl[f][1], bl[f][2], bl[f][3],
                          bB + swz128(bO[f] + kso + 64));
                #pragma unroll
                for (int im = 0; im < 4; im++)
                    #pragma unroll
                    for (int jn = 0; jn < 8; jn++)
                        mma_bf16(acc[im][jn], ah[im],
                                 bl[jn >> 1][(jn & 1) * 2], bl[jn >> 1][(jn & 1) * 2 + 1]);
            }
        }
    }

    // ---- epilogue ----
    if (mode == 2) {
        // v: transpose via SMEM bounce, emit v^T split bf16 into Cvt.
        __syncthreads();                       // smem stages now free
        float* tf = (float*)smem;              // [256][129] fp32
        #pragma unroll
        for (int im = 0; im < 4; im++) {
            const int rl = wm * 64 + im * 16 + (lane >> 2);
            #pragma unroll
            for (int jn = 0; jn < 8; jn++) {
                const int cl = wn * 64 + jn * 8 + (lane & 3) * 2;
                tf[(size_t)cl * 129 + rl]           = acc[im][jn][0];
                tf[(size_t)(cl + 1) * 129 + rl]     = acc[im][jn][1];
                tf[(size_t)cl * 129 + rl + 8]       = acc[im][jn][2];
                tf[(size_t)(cl + 1) * 129 + rl + 8] = acc[im][jn][3];
            }
        }
        __syncthreads();
        const int b   = m0 >> 11;
        const int s0l = m0 & 2047;
        const int d   = n0 + tid;
        __nv_bfloat16* dst = Cvt + ((size_t)b * DD + d) * 2 * SS + s0l;
        const float* rowf = tf + (size_t)tid * 129;
        #pragma unroll 8
        for (int m = 0; m < 128; m += 2) {
            const float v0 = rowf[m], v1 = rowf[m + 1];
            const __nv_bfloat16 h0 = __float2bfloat16(v0);
            const __nv_bfloat16 l0 = __float2bfloat16(v0 - __bfloat162float(h0));
            const __nv_bfloat16 h1 = __float2bfloat16(v1);
            const __nv_bfloat16 l1 = __float2bfloat16(v1 - __bfloat162float(h1));
            *(__nv_bfloat162*)(dst + m)      = __halves2bfloat162(h0, h1);
            *(__nv_bfloat162*)(dst + SS + m) = __halves2bfloat162(l0, l1);
        }
        return;
    }

    #pragma unroll
    for (int im = 0; im < 4; im++) {
        const int r = m0 + wm * 64 + im * 16 + (lane >> 2);
        #pragma unroll
        for (int jn = 0; jn < 8; jn++) {
            const int cc = n0 + wn * 64 + jn * 8 + (lane & 3) * 2;
            if (mode == 0) {
                float* Cg = (float*)Cv;
                *(float2*)(Cg + (size_t)r * N_C + cc)       = make_float2(acc[im][jn][0], acc[im][jn][1]);
                *(float2*)(Cg + (size_t)(r + 8) * N_C + cc) = make_float2(acc[im][jn][2], acc[im][jn][3]);
            } else {
                __nv_bfloat16* Cg = (__nv_bfloat16*)Cv;
                #pragma unroll
                for (int hr = 0; hr < 2; hr++) {
                    const float v0 = acc[im][jn][hr * 2];
                    const float v1 = acc[im][jn][hr * 2 + 1];
                    const __nv_bfloat16 h0 = __float2bfloat16(v0);
                    const __nv_bfloat16 l0 = __float2bfloat16(v0 - __bfloat162float(h0));
                    const __nv_bfloat16 h1 = __float2bfloat16(v1);
                    const __nv_bfloat16 l1 = __float2bfloat16(v1 - __bfloat162float(h1));
                    __nv_bfloat16* row = Cg + (size_t)(r + hr * 8) * (2 * N_C);
                    *(__nv_bfloat162*)(row + cc)       = __halves2bfloat162(h0, h1);
                    *(__nv_bfloat162*)(row + N_C + cc) = __halves2bfloat162(l0, l1);
                }
            }
        }
    }
}

// ---------------------------------------------------------------------------
// AV kernel: round-8 128x128 fused-pass GEMM, 128 threads = 4 warps of 64x64,
// K clamped at the diagonal block, longest tiles first. C fp32.
// ---------------------------------------------------------------------------
#define AV_STAGE 32768
#define AV_SMEM (3 * AV_STAGE)

__global__ __launch_bounds__(128, 2)
void gemm_av(const __nv_bfloat16* __restrict__ A,
             const __nv_bfloat16* __restrict__ B,
             float* __restrict__ C)
{
    extern __shared__ __align__(1024) char smem[];
    const uint32_t base0 = (uint32_t)__cvta_generic_to_shared(smem);

    const int tid  = threadIdx.x;
    const int wid  = tid >> 5;
    const int lane = tid & 31;
    const int wm   = wid >> 1;
    const int wn   = wid & 1;

    const int t    = blockIdx.x;
    const int m    = 15 - (t >> 5);
    const int rest = t & 31;
    const int m0 = m * 128, n0 = (rest & 7) * 128;
    const int z  = rest >> 3;
    const __nv_bfloat16* Ag = A + (size_t)z * SS * 2 * SS;
    const __nv_bfloat16* Bg = B + (size_t)z * DD * 2 * SS;
    float* Cv = C + (size_t)z * SS * DD;
    const int rowL = 2 * SS, P = SS;
    const int nC = min(SS / 32, 4 * m + 4);

    const int mo  = ((lane >> 3) & 1) * 8 + (lane & 7);
    const int akb = ((lane >> 4) & 1) * 16;
    const int no  = ((lane >> 4) & 1) * 8 + (lane & 7);
    const int bkb = ((lane >> 3) & 1) * 16;
    uint32_t aO[4], bO[4];
    #pragma unroll
    for (int f = 0; f < 4; f++) {
        aO[f] = (uint32_t)((wm * 64 + f * 16 + mo) * 128 + akb);
        bO[f] = (uint32_t)((wn * 64 + f * 16 + no) * 128 + bkb);
    }

    float acc[4][8][4];
    #pragma unroll
    for (int i = 0; i < 4; i++)
        #pragma unroll
        for (int j = 0; j < 8; j++)
            #pragma unroll
            for (int q = 0; q < 4; q++) acc[i][j][q] = 0.0f;

    auto load_chunk = [&](int c) {
        const int st = c % 3;
        const uint32_t aBase = base0 + st * AV_STAGE;
        const uint32_t bBase = aBase + 16384;
        const __nv_bfloat16* ah = Ag + (size_t)(m0 + tid) * rowL + c * 32;
        const __nv_bfloat16* bh = Bg + (size_t)(n0 + tid) * rowL + c * 32;
        const uint32_t ro = (uint32_t)tid * 128;
        #pragma unroll
        for (int s4 = 0; s4 < 4; s4++) {
            cp16(aBase + swz128(ro + s4 * 16),      ah + s4 * 8);
            cp16(aBase + swz128(ro + 64 + s4 * 16), ah + P + s4 * 8);
            cp16(bBase + swz128(ro + s4 * 16),      bh + s4 * 8);
            cp16(bBase + swz128(ro + 64 + s4 * 16), bh + P + s4 * 8);
        }
        asm volatile("cp.async.commit_group;\n");
    };

    load_chunk(0);
    if (nC > 1) load_chunk(1);

    for (int c = 0; c < nC; ++c) {
        if (c + 1 < nC) asm volatile("cp.async.wait_group 1;\n" ::: "memory");
        else            asm volatile("cp.async.wait_group 0;\n" ::: "memory");
        __syncthreads();

        if (c + 2 < nC) load_chunk(c + 2);

        const uint32_t aB = base0 + (c % 3) * AV_STAGE;
        const uint32_t bB = aB + 16384;

        #pragma unroll
        for (int ks = 0; ks < 2; ks++) {
            const uint32_t kso = (uint32_t)(ks * 32);
            uint32_t ah[4][4], bh[4][4];
            #pragma unroll
            for (int f = 0; f < 4; f++)
                ldsm4(ah[f][0], ah[f][1], ah[f][2], ah[f][3], aB + swz128(aO[f] + kso));
            #pragma unroll
            for (int f = 0; f < 4; f++)
                ldsm4(bh[f][0], bh[f][1], bh[f][2], bh[f][3], bB + swz128(bO[f] + kso));
            {
                uint32_t al[4][4];
                #pragma unroll
                for (int f = 0; f < 4; f++)
                    ldsm4(al[f][0], al[f][1], al[f][2], al[f][3],
                          aB + swz128(aO[f] + kso + 64));
                #pragma unroll
                for (int im = 0; im < 4; im++)
                    #pragma unroll
                    for (int jn = 0; jn < 8; jn++)
                        mma_bf16(acc[im][jn], ah[im],
                                 bh[jn >> 1][(jn & 1) * 2], bh[jn >> 1][(jn & 1) * 2 + 1]);
                #pragma unroll
                for (int im = 0; im < 4; im++)
                    #pragma unroll
                    for (int jn = 0; jn < 8; jn++)
                        mma_bf16(acc[im][jn], al[im],
                                 bh[jn >> 1][(jn & 1) * 2], bh[jn >> 1][(jn & 1) * 2 + 1]);
            }
            {
                uint32_t bl[4][4];
                #pragma unroll
                for (int f = 0; f < 4; f++)
                    ldsm4(bl[f][0], bl[f][1], bl[f][2], bl[f][3],
                          bB + swz128(bO[f] + kso + 64));
                #pragma unroll
                for (int im = 0; im < 4; im++)
                    #pragma unroll
                    for (int jn = 0; jn < 8; jn++)
                        mma_bf16(acc[im][jn], ah[im],
                                 bl[jn >> 1][(jn & 1) * 2], bl[jn >> 1][(jn & 1) * 2 + 1]);
            }
        }
    }

    #pragma unroll
    for (int im = 0; im < 4; im++) {
        const int r = m0 + wm * 64 + im * 16 + (lane >> 2);
        #pragma unroll
        for (int jn = 0; jn < 8; jn++) {
            const int cc = n0 + wn * 64 + jn * 8 + (lane & 3) * 2;
            *(float2*)(Cv + (size_t)r * DD + cc)       = make_float2(acc[im][jn][0], acc[im][jn][1]);
            *(float2*)(Cv + (size_t)(r + 8) * DD + cc) = make_float2(acc[im][jn][2], acc[im][jn][3]);
        }
    }
}

// ---------------------------------------------------------------------------
// fp32 -> [hi | lo] bf16 split, same row layout (row len 2K).
// ---------------------------------------------------------------------------
__global__ __launch_bounds__(256)
void conv_split2(const float* __restrict__ src, __nv_bfloat16* __restrict__ dst, int K)
{
    const long long idx = (long long)blockIdx.x * 256 + threadIdx.x;
    const long long m = idx / K;
    const int j = (int)(idx % K);
    const float v = src[idx];
    const __nv_bfloat16 h = __float2bfloat16(v);
    const __nv_bfloat16 l = __float2bfloat16(v - __bfloat162float(h));
    __nv_bfloat16* o = dst + m * 2LL * K;
    o[j] = h; o[K + j] = l;
}

// ---------------------------------------------------------------------------
// Merged weight transpose: fp32 [D][D] -> split bf16 [D][2D], 3 weights via z.
// ---------------------------------------------------------------------------
__global__ __launch_bounds__(256)
void transposeW(const float* __restrict__ s0, const float* __restrict__ s1,
                const float* __restrict__ s2,
                __nv_bfloat16* __restrict__ d0, __nv_bfloat16* __restrict__ d1,
                __nv_bfloat16* __restrict__ d2)
{
    __shared__ float tile[32][33];
    const int z = blockIdx.z;
    const float* src = (z == 0) ? s0 : ((z == 1) ? s1 : s2);
    __nv_bfloat16* dst = (z == 0) ? d0 : ((z == 1) ? d1 : d2);
    const int r0 = blockIdx.y * 32, c0 = blockIdx.x * 32;
    const int tx = threadIdx.x & 31;
    const int ty = threadIdx.x >> 5;

    #pragma unroll
    for (int dy = 0; dy < 32; dy += 8)
        tile[ty + dy][tx] = src[(size_t)(r0 + ty + dy) * DD + c0 + tx];
    __syncthreads();

    #pragma unroll
    for (int dy = 0; dy < 32; dy += 8) {
        const int c = c0 + ty + dy;
        const int r = r0 + tx;
        const float v = tile[tx][ty + dy];
        const __nv_bfloat16 h = __float2bfloat16(v);
        const __nv_bfloat16 l = __float2bfloat16(v - __bfloat162float(h));
        __nv_bfloat16* o = dst + (size_t)c * 2 * DD;
        o[r] = h; o[DD + r] = l;
    }
}

// ---------------------------------------------------------------------------
// Causal softmax emitting split bf16 attn [hi | lo]. Zero-fills only up to the
// 128-row diagonal-block boundary (AV K-clamp never reads past it).
// ---------------------------------------------------------------------------
__global__ __launch_bounds__(256)
void softmax2(const float* __restrict__ Sc, __nv_bfloat16* __restrict__ A3,
              int S, float scale)
{
    const long long row = blockIdx.x;            // b*S + i
    const int i = (int)(row % S);
    const float* p = Sc + row * (long long)S;
    __nv_bfloat16* out = A3 + row * (long long)(2 * S);
    const int L = i + 1;
    const int Lz = ((i >> 7) + 1) << 7;          // diagonal-block end

    const int tid  = threadIdx.x;
    const int lane = tid & 31;
    const int wid  = tid >> 5;
    __shared__ float red[32];

    float mx = -INFINITY;
    for (int j = tid; j < L; j += 256) mx = fmaxf(mx, p[j]);
    #pragma unroll
    for (int o = 16; o; o >>= 1) mx = fmaxf(mx, __shfl_xor_sync(0xffffffffu, mx, o));
    if (lane == 0) red[wid] = mx;
    __syncthreads();
    if (tid == 0) {
        float m = red[0];
        #pragma unroll
        for (int w = 1; w < 8; w++) m = fmaxf(m, red[w]);
        red[0] = m;
    }
    __syncthreads();
    mx = red[0];
    __syncthreads();

    float e[8];
    float sum = 0.0f;
    int cnt = 0;
    for (int j = tid; j < L; j += 256) {
        const float ev = __expf((p[j] - mx) * scale);
        e[cnt++] = ev;
        sum += ev;
    }
    #pragma unroll
    for (int o = 16; o; o >>= 1) sum += __shfl_xor_sync(0xffffffffu, sum, o);
    if (lane == 0) red[wid] = sum;
    __syncthreads();
    if (tid == 0) {
        float s = red[0];
        #pragma unroll
        for (int w = 1; w < 8; w++) s += red[w];
        red[0] = s;
    }
    __syncthreads();
    const float inv = 1.0f / red[0];

    cnt = 0;
    for (int j = tid; j < L; j += 256) {
        const float v = e[cnt++] * inv;
        const __nv_bfloat16 h = __float2bfloat16(v);
        const __nv_bfloat16 l = __float2bfloat16(v - __bfloat162float(h));
        out[j] = h; out[S + j] = l;
    }
    const __nv_bfloat16 zero = __float2bfloat16(0.0f);
    for (int j = L + tid; j < Lz; j += 256) {
        out[j] = zero; out[S + j] = zero;
    }
}

// ---------------------------------------------------------------------------
extern "C" void kernel_launch(void* const* d_in, const int* in_sizes, int n_in,
                              void* d_out, int out_size)
{
    (void)in_sizes; (void)n_in; (void)out_size;
    const float* x  = (const float*)d_in[0];
    const float* Wq = (const float*)d_in[1];
    const float* Wk = (const float*)d_in[2];
    const float* Wv = (const float*)d_in[3];
    float* out = (float*)d_out;

    __nv_bfloat16 *x3, *wqt, *wkt, *wvt, *q3, *k3, *vt3, *a3;
    float *s;
    cudaGetSymbolAddress((void**)&x3,  g_x3);
    cudaGetSymbolAddress((void**)&wqt, g_wqt);
    cudaGetSymbolAddress((void**)&wkt, g_wkt);
    cudaGetSymbolAddress((void**)&wvt, g_wvt);
    cudaGetSymbolAddress((void**)&q3,  g_q3);
    cudaGetSymbolAddress((void**)&k3,  g_k3);
    cudaGetSymbolAddress((void**)&vt3, g_vt3);
    cudaGetSymbolAddress((void**)&s,   g_s);
    cudaGetSymbolAddress((void**)&a3,  g_a3);

    cudaFuncSetAttribute(gemm_big, cudaFuncAttributeMaxDynamicSharedMemorySize, BIG_SMEM);
    cudaFuncSetAttribute(gemm_av,  cudaFuncAttributeMaxDynamicSharedMemorySize, AV_SMEM);

    const int B = BB, S = SS, D = DD;
    const long long MS = (long long)B * S;   // 8192

    // launch 0: x conversion
    conv_split2<<<(int)(MS * D / 256), 256>>>(x, x3, D);

    // launch 1: merged weight transposes
    {
        dim3 tg(D / 32, D / 32, 3);
        transposeW<<<tg, 256>>>(Wq, Wk, Wv, wqt, wkt, wvt);
    }

    // launch 2: fused QKV projections (768 tiles of 128x256); v epilogue
    //           writes v^T split directly (no transposeV pass)
    gemm_big<<<768, 256, BIG_SMEM>>>(1, x3, wqt, wkt, wvt, q3, k3, vt3);

    // launch 3 (ncu-captured): scores = Q K^T, triangular 128x256 tiles
    gemm_big<<<72 * B, 256, BIG_SMEM>>>(2, q3, k3, nullptr, nullptr,
                                        s, nullptr, nullptr);

    // launch 4: softmax -> split bf16 attn
    softmax2<<<B * S, 256>>>(s, a3, S, 0.03125f);

    // launch 5: out = attn @ V (K-clamped, longest tiles first)
    gemm_av<<<16 * 8 * B, 128, AV_SMEM>>>(a3, vt3, out);
}

// round 11
// speedup vs baseline: 1.4263x; 1.3825x over previous
#include <cuda_runtime.h>
#include <cuda_fp16.h>
#include <cstdint>
#include <math.h>

#define BB 4
#define SS 2048
#define DD 1024

// ---------------------------------------------------------------------------
// Scratch (device globals — allocation-free per harness rules)
// A-side operands: fp16 split [hi(K) | lo(K)], row length 2K (22-bit value).
// B-side operands: plain fp16 (hi only) — the 2-pass scheme (Ah+Al)*Bh is
// exactly A(22b) x fp16(B); B rounding (~1.6e-4 rms) is the only error.
// ---------------------------------------------------------------------------
__device__ __half g_x3 [(size_t)BB * SS * 2 * DD];   // x split      [8192][2048]
__device__ __half g_wqt[(size_t)DD * DD];            // Wq^T fp16    [1024][1024]
__device__ __half g_wkt[(size_t)DD * DD];
__device__ __half g_wvt[(size_t)DD * DD];
__device__ __half g_q3 [(size_t)BB * SS * 2 * DD];   // q split (A-side of scores)
__device__ __half g_k3h[(size_t)BB * SS * DD];       // k fp16 hi-only (B-side)
__device__ float  g_vf [(size_t)BB * SS * DD];       // v fp32
__device__ __half g_vt [(size_t)BB * DD * SS];       // v^T fp16 hi-only (B-side)
__device__ float  g_s  [(size_t)BB * SS * SS];       // raw scores fp32
__device__ __half g_a3 [(size_t)BB * SS * 2 * SS];   // attn split (A-side of AV)

// ---------------------------------------------------------------------------
// PTX helpers (compute_103-safe: cp.async, ldmatrix, mma.sync only)
// ---------------------------------------------------------------------------
__device__ __forceinline__ void cp16(uint32_t dst, const void* src) {
    asm volatile("cp.async.cg.shared.global [%0], [%1], 16;\n" :: "r"(dst), "l"(src));
}
__device__ __forceinline__ uint32_t swz128(uint32_t off) { return off ^ ((off >> 3) & 0x70); }
__device__ __forceinline__ uint32_t swz64 (uint32_t off) { return off ^ ((off >> 3) & 0x30); }

__device__ __forceinline__ void ldsm4(uint32_t& r0, uint32_t& r1, uint32_t& r2, uint32_t& r3,
                                      uint32_t addr) {
    asm volatile("ldmatrix.sync.aligned.m8n8.x4.shared.b16 {%0,%1,%2,%3}, [%4];"
                 : "=r"(r0), "=r"(r1), "=r"(r2), "=r"(r3) : "r"(addr));
}

__device__ __forceinline__ void mma_f16(float c[4], const uint32_t a[4], const uint32_t b0,
                                        const uint32_t b1) {
    asm volatile(
        "mma.sync.aligned.m16n8k16.row.col.f32.f16.f16.f32 "
        "{%0,%1,%2,%3}, {%4,%5,%6,%7}, {%8,%9}, {%0,%1,%2,%3};\n"
        : "+f"(c[0]), "+f"(c[1]), "+f"(c[2]), "+f"(c[3])
        : "r"(a[0]), "r"(a[1]), "r"(a[2]), "r"(a[3]), "r"(b0), "r"(b1));
}

// ---------------------------------------------------------------------------
// Unified 2-pass fp16 GEMM. CTA tile 128x128, chunk = 32 logical k.
// SMEM per chunk: A 128 rows x 128B ([hi 64B | lo 64B], swz128) = 16KB,
//                 B 128 rows x  64B (hi only, swz64)            =  8KB.
// acc += Ah*Bh + Al*Bh  ==  A(22-bit) * Bh.
// 3-stage cp.async, 128 threads = 4 warps of 64x64.
// sched 1: fused QKV  — A=x3; B = Wq^T/Wk^T/Wv^T (w=t>>9).
//          C: q -> fp16 split (mode1), k -> fp16 hi (mode3), v -> fp32 (mode0)
// sched 2: scores QK^T — A=q3 split, B=k3h; triangular list (136/batch)
// sched 3: attn @ V    — A=a3 split, B=vt; K-clamped, longest-first
// ---------------------------------------------------------------------------
#define STAGE2 24576
#define GEMM_SMEM (3 * STAGE2)       // 73728

__global__ __launch_bounds__(128, 2)
void gemm2p(int sched,
            const __half* __restrict__ A,
            const __half* __restrict__ B0,
            const __half* __restrict__ B1,
            const __half* __restrict__ B2,
            void* __restrict__ C0, void* __restrict__ C1, void* __restrict__ C2)
{
    extern __shared__ __align__(1024) char smem[];
    const uint32_t base0 = (uint32_t)__cvta_generic_to_shared(smem);

    const int tid  = threadIdx.x;
    const int wid  = tid >> 5;
    const int lane = tid & 31;
    const int wm   = wid >> 1;      // 0..1
    const int wn   = wid & 1;       // 0..1

    // ---- decode tile ----
    const int t = blockIdx.x;
    const __half *Ag, *Bg;
    void* Cv;
    int m0, n0, N_C, rowL, rowB, nC, mode, P;
    if (sched == 1) {                       // fused QKV
        const int w = t >> 9;
        const int r = t & 511;
        m0 = (r >> 3) * 128; n0 = (r & 7) * 128;
        Ag = A;
        Bg = (w == 0) ? B0 : ((w == 1) ? B1 : B2);
        Cv = (w == 0) ? C0 : ((w == 1) ? C1 : C2);
        mode = (w == 0) ? 1 : ((w == 1) ? 3 : 0);
        N_C = DD; rowL = 2 * DD; rowB = DD; nC = DD / 32; P = DD;
    } else if (sched == 2) {                // scores, triangular decode
        const int z  = t / 136;
        const int tt = t - z * 136;
        int r = (int)floorf((sqrtf(8.0f * tt + 1.0f) - 1.0f) * 0.5f);
        while ((r + 1) * (r + 2) / 2 <= tt) r++;
        while (r * (r + 1) / 2 > tt) r--;
        const int c = tt - r * (r + 1) / 2;
        m0 = r * 128; n0 = c * 128;
        Ag = A  + (size_t)z * SS * 2 * DD;
        Bg = B0 + (size_t)z * SS * DD;
        Cv = (float*)C0 + (size_t)z * SS * SS;
        mode = 0; N_C = SS; rowL = 2 * DD; rowB = DD; nC = DD / 32; P = DD;
    } else {                                // attn @ V, longest-first
        const int m    = 15 - (t >> 5);
        const int rest = t & 31;
        m0 = m * 128; n0 = (rest & 7) * 128;
        const int z = rest >> 3;
        Ag = A  + (size_t)z * SS * 2 * SS;
        Bg = B0 + (size_t)z * DD * SS;
        Cv = (float*)C0 + (size_t)z * SS * DD;
        mode = 0; N_C = DD; rowL = 2 * SS; rowB = SS;
        nC = min(SS / 32, 4 * m + 4); P = SS;
    }

    // ldmatrix base offsets
    const int mo  = ((lane >> 3) & 1) * 8 + (lane & 7);
    const int akb = ((lane >> 4) & 1) * 16;
    const int no  = ((lane >> 4) & 1) * 8 + (lane & 7);
    const int bkb = ((lane >> 3) & 1) * 16;
    uint32_t aO[4], bO[4];
    #pragma unroll
    for (int f = 0; f < 4; f++) {
        aO[f] = (uint32_t)((wm * 64 + f * 16 + mo) * 128 + akb);   // 128B rows
        bO[f] = (uint32_t)((wn * 64 + f * 16 + no) * 64 + bkb);    // 64B rows
    }

    float acc[4][8][4];
    #pragma unroll
    for (int i = 0; i < 4; i++)
        #pragma unroll
        for (int j = 0; j < 8; j++)
            #pragma unroll
            for (int q = 0; q < 4; q++) acc[i][j][q] = 0.0f;

    // chunk loader: thread t loads A row m0+t (hi+lo, 8 cp16) and
    // B row n0+t (hi, 4 cp16).
    auto load_chunk = [&](int c) {
        const int st = c % 3;
        const uint32_t aBase = base0 + st * STAGE2;
        const uint32_t bBase = aBase + 16384;
        const __half* as = Ag + (size_t)(m0 + tid) * rowL + c * 32;
        const __half* bs = Bg + (size_t)(n0 + tid) * rowB + c * 32;
        const uint32_t roA = (uint32_t)tid * 128;
        const uint32_t roB = (uint32_t)tid * 64;
        #pragma unroll
        for (int s4 = 0; s4 < 4; s4++) {
            cp16(aBase + swz128(roA + s4 * 16),      as + s4 * 8);
            cp16(aBase + swz128(roA + 64 + s4 * 16), as + P + s4 * 8);
            cp16(bBase + swz64(roB + s4 * 16),       bs + s4 * 8);
        }
        asm volatile("cp.async.commit_group;\n");
    };

    load_chunk(0);
    if (nC > 1) load_chunk(1);

    for (int c = 0; c < nC; ++c) {
        if (c + 1 < nC) asm volatile("cp.async.wait_group 1;\n" ::: "memory");
        else            asm volatile("cp.async.wait_group 0;\n" ::: "memory");
        __syncthreads();

        if (c + 2 < nC) load_chunk(c + 2);

        const uint32_t aB = base0 + (c % 3) * STAGE2;
        const uint32_t bB = aB + 16384;

        #pragma unroll
        for (int ks = 0; ks < 2; ks++) {
            const uint32_t kso = (uint32_t)(ks * 32);
            uint32_t ah[4][4], bh[4][4], al[4][4];
            #pragma unroll
            for (int f = 0; f < 4; f++)
                ldsm4(ah[f][0], ah[f][1], ah[f][2], ah[f][3], aB + swz128(aO[f] + kso));
            #pragma unroll
            for (int f = 0; f < 4; f++)
                ldsm4(bh[f][0], bh[f][1], bh[f][2], bh[f][3], bB + swz64(bO[f] + kso));
            #pragma unroll
            for (int f = 0; f < 4; f++)
                ldsm4(al[f][0], al[f][1], al[f][2], al[f][3], aB + swz128(aO[f] + kso + 64));

            // pass 1: Ah * Bh
            #pragma unroll
            for (int im = 0; im < 4; im++)
                #pragma unroll
                for (int jn = 0; jn < 8; jn++)
                    mma_f16(acc[im][jn], ah[im],
                            bh[jn >> 1][(jn & 1) * 2], bh[jn >> 1][(jn & 1) * 2 + 1]);
            // pass 2: Al * Bh
            #pragma unroll
            for (int im = 0; im < 4; im++)
                #pragma unroll
                for (int jn = 0; jn < 8; jn++)
                    mma_f16(acc[im][jn], al[im],
                            bh[jn >> 1][(jn & 1) * 2], bh[jn >> 1][(jn & 1) * 2 + 1]);
        }
    }

    // ---- epilogue ----
    #pragma unroll
    for (int im = 0; im < 4; im++) {
        const int r = m0 + wm * 64 + im * 16 + (lane >> 2);
        #pragma unroll
        for (int jn = 0; jn < 8; jn++) {
            const int cc = n0 + wn * 64 + jn * 8 + (lane & 3) * 2;
            if (mode == 0) {
                float* Cg = (float*)Cv;
                *(float2*)(Cg + (size_t)r * N_C + cc)       = make_float2(acc[im][jn][0], acc[im][jn][1]);
                *(float2*)(Cg + (size_t)(r + 8) * N_C + cc) = make_float2(acc[im][jn][2], acc[im][jn][3]);
            } else if (mode == 1) {
                __half* Cg = (__half*)Cv;
                #pragma unroll
                for (int hr = 0; hr < 2; hr++) {
                    const float v0 = acc[im][jn][hr * 2];
                    const float v1 = acc[im][jn][hr * 2 + 1];
                    const __half h0 = __float2half(v0);
                    const __half l0 = __float2half(v0 - __half2float(h0));
                    const __half h1 = __float2half(v1);
                    const __half l1 = __float2half(v1 - __half2float(h1));
                    __half* row = Cg + (size_t)(r + hr * 8) * (2 * N_C);
                    *(__half2*)(row + cc)       = __halves2half2(h0, h1);
                    *(__half2*)(row + N_C + cc) = __halves2half2(l0, l1);
                }
            } else {   // mode 3: fp16 hi-only (k)
                __half* Cg = (__half*)Cv;
                #pragma unroll
                for (int hr = 0; hr < 2; hr++) {
                    const __half h0 = __float2half(acc[im][jn][hr * 2]);
                    const __half h1 = __float2half(acc[im][jn][hr * 2 + 1]);
                    *(__half2*)(Cg + (size_t)(r + hr * 8) * N_C + cc) = __halves2half2(h0, h1);
                }
            }
        }
    }
}

// ---------------------------------------------------------------------------
// fp32 -> [hi | lo] fp16 split, row length 2K.
// ---------------------------------------------------------------------------
__global__ __launch_bounds__(256)
void conv_split2(const float* __restrict__ src, __half* __restrict__ dst, int K)
{
    const long long idx = (long long)blockIdx.x * 256 + threadIdx.x;
    const long long m = idx / K;
    const int j = (int)(idx % K);
    const float v = src[idx];
    const __half h = __float2half(v);
    const __half l = __float2half(v - __half2float(h));
    __half* o = dst + m * 2LL * K;
    o[j] = h; o[K + j] = l;
}

// ---------------------------------------------------------------------------
// Merged weight transpose: fp32 [D][D] -> fp16 [D][D] (hi only), 3 via z.
// ---------------------------------------------------------------------------
__global__ __launch_bounds__(256)
void transposeW(const float* __restrict__ s0, const float* __restrict__ s1,
                const float* __restrict__ s2,
                __half* __restrict__ d0, __half* __restrict__ d1,
                __half* __restrict__ d2)
{
    __shared__ float tile[32][33];
    const int z = blockIdx.z;
    const float* src = (z == 0) ? s0 : ((z == 1) ? s1 : s2);
    __half*      dst = (z == 0) ? d0 : ((z == 1) ? d1 : d2);
    const int r0 = blockIdx.y * 32, c0 = blockIdx.x * 32;
    const int tx = threadIdx.x & 31;
    const int ty = threadIdx.x >> 5;

    #pragma unroll
    for (int dy = 0; dy < 32; dy += 8)
        tile[ty + dy][tx] = src[(size_t)(r0 + ty + dy) * DD + c0 + tx];
    __syncthreads();

    #pragma unroll
    for (int dy = 0; dy < 32; dy += 8) {
        const int c = c0 + ty + dy;
        const int r = r0 + tx;
        dst[(size_t)c * DD + r] = __float2half(tile[tx][ty + dy]);
    }
}

// ---------------------------------------------------------------------------
// v transpose: fp32 [S][D] per batch -> fp16 [D][S] (hi only)
// ---------------------------------------------------------------------------
__global__ __launch_bounds__(256)
void transposeV(const float* __restrict__ src, __half* __restrict__ dst)
{
    __shared__ float tile[32][33];
    src += (size_t)blockIdx.z * SS * DD;
    dst += (size_t)blockIdx.z * DD * SS;
    const int r0 = blockIdx.y * 32, c0 = blockIdx.x * 32;
    const int tx = threadIdx.x & 31;
    const int ty = threadIdx.x >> 5;

    #pragma unroll
    for (int dy = 0; dy < 32; dy += 8)
        tile[ty + dy][tx] = src[(size_t)(r0 + ty + dy) * DD + c0 + tx];
    __syncthreads();

    #pragma unroll
    for (int dy = 0; dy < 32; dy += 8) {
        const int c = c0 + ty + dy;
        const int r = r0 + tx;
        dst[(size_t)c * SS + r] = __float2half(tile[tx][ty + dy]);
    }
}

// ---------------------------------------------------------------------------
// Causal softmax emitting fp16 split attn [hi | lo]. Zero-fills only up to
// the 128-row diagonal-block boundary (AV K-clamp never reads past it).
// ---------------------------------------------------------------------------
__global__ __launch_bounds__(256)
void softmax2(const float* __restrict__ Sc, __half* __restrict__ A3,
              int S, float scale)
{
    const long long row = blockIdx.x;            // b*S + i
    const int i = (int)(row % S);
    const float* p = Sc + row * (long long)S;
    __half* out = A3 + row * (long long)(2 * S);
    const int L = i + 1;
    const int Lz = ((i >> 7) + 1) << 7;          // diagonal-block end

    const int tid  = threadIdx.x;
    const int lane = tid & 31;
    const int wid  = tid >> 5;
    __shared__ float red[32];

    float mx = -INFINITY;
    for (int j = tid; j < L; j += 256) mx = fmaxf(mx, p[j]);
    #pragma unroll
    for (int o = 16; o; o >>= 1) mx = fmaxf(mx, __shfl_xor_sync(0xffffffffu, mx, o));
    if (lane == 0) red[wid] = mx;
    __syncthreads();
    if (tid == 0) {
        float m = red[0];
        #pragma unroll
        for (int w = 1; w < 8; w++) m = fmaxf(m, red[w]);
        red[0] = m;
    }
    __syncthreads();
    mx = red[0];
    __syncthreads();

    float e[8];
    float sum = 0.0f;
    int cnt = 0;
    for (int j = tid; j < L; j += 256) {
        const float ev = __expf((p[j] - mx) * scale);
        e[cnt++] = ev;
        sum += ev;
    }
    #pragma unroll
    for (int o = 16; o; o >>= 1) sum += __shfl_xor_sync(0xffffffffu, sum, o);
    if (lane == 0) red[wid] = sum;
    __syncthreads();
    if (tid == 0) {
        float s = red[0];
        #pragma unroll
        for (int w = 1; w < 8; w++) s += red[w];
        red[0] = s;
    }
    __syncthreads();
    const float inv = 1.0f / red[0];

    cnt = 0;
    for (int j = tid; j < L; j += 256) {
        const float v = e[cnt++] * inv;
        const __half h = __float2half(v);
        const __half l = __float2half(v - __half2float(h));
        out[j] = h; out[S + j] = l;
    }
    const __half zero = __float2half(0.0f);
    for (int j = L + tid; j < Lz; j += 256) {
        out[j] = zero; out[S + j] = zero;
    }
}

// ---------------------------------------------------------------------------
extern "C" void kernel_launch(void* const* d_in, const int* in_sizes, int n_in,
                              void* d_out, int out_size)
{
    (void)in_sizes; (void)n_in; (void)out_size;
    const float* x  = (const float*)d_in[0];
    const float* Wq = (const float*)d_in[1];
    const float* Wk = (const float*)d_in[2];
    const float* Wv = (const float*)d_in[3];
    float* out = (float*)d_out;

    __half *x3, *wqt, *wkt, *wvt, *q3, *k3h, *vt, *a3;
    float *vf, *s;
    cudaGetSymbolAddress((void**)&x3,  g_x3);
    cudaGetSymbolAddress((void**)&wqt, g_wqt);
    cudaGetSymbolAddress((void**)&wkt, g_wkt);
    cudaGetSymbolAddress((void**)&wvt, g_wvt);
    cudaGetSymbolAddress((void**)&q3,  g_q3);
    cudaGetSymbolAddress((void**)&k3h, g_k3h);
    cudaGetSymbolAddress((void**)&vf,  g_vf);
    cudaGetSymbolAddress((void**)&vt,  g_vt);
    cudaGetSymbolAddress((void**)&s,   g_s);
    cudaGetSymbolAddress((void**)&a3,  g_a3);

    cudaFuncSetAttribute(gemm2p, cudaFuncAttributeMaxDynamicSharedMemorySize, GEMM_SMEM);

    const int B = BB, S = SS, D = DD;
    const long long MS = (long long)B * S;   // 8192

    // launch 0: x conversion -> fp16 split
    conv_split2<<<(int)(MS * D / 256), 256>>>(x, x3, D);

    // launch 1: merged weight transposes -> fp16 hi
    {
        dim3 tg(D / 32, D / 32, 3);
        transposeW<<<tg, 256>>>(Wq, Wk, Wv, wqt, wkt, wvt);
    }

    // launch 2: fused QKV (1536 tiles). q -> fp16 split, k -> fp16 hi, v -> fp32
    gemm2p<<<1536, 128, GEMM_SMEM>>>(1, x3, wqt, wkt, wvt, q3, k3h, vf);

    // launch 3 (ncu-captured): scores = Q K^T, triangular tile list
    gemm2p<<<136 * B, 128, GEMM_SMEM>>>(2, q3, k3h, nullptr, nullptr,
                                        s, nullptr, nullptr);

    // launch 4: v transpose -> fp16 hi
    {
        dim3 tg(D / 32, S / 32, B);
        transposeV<<<tg, 256>>>(vf, vt);
    }

    // launch 5: softmax -> fp16 split attn
    softmax2<<<B * S, 256>>>(s, a3, S, 0.03125f);

    // launch 6: out = attn @ V (K-clamped, longest tiles first)
    gemm2p<<<16 * 8 * B, 128, GEMM_SMEM>>>(3, a3, vt, nullptr, nullptr,
                                           out, nullptr, nullptr);
}

// round 12
// speedup vs baseline: 2.2825x; 1.6003x over previous
#include <cuda_runtime.h>
#include <cuda_fp16.h>
#include <cstdint>
#include <math.h>

#define BB 4
#define SS 2048
#define DD 1024

// ---------------------------------------------------------------------------
// Scratch (device globals — allocation-free per harness rules)
// All operands plain fp16 (1-pass scheme). Calibrated error model:
// ~10 incoherent fp16-rounding components x 1.88e-4 -> ~6e-4 << 1e-3 gate.
// ---------------------------------------------------------------------------
__device__ __half g_xh [(size_t)BB * SS * DD];       // x fp16    [8192][1024]
__device__ __half g_wqt[(size_t)DD * DD];            // Wq^T fp16 [1024][1024]
__device__ __half g_wkt[(size_t)DD * DD];
__device__ __half g_wvt[(size_t)DD * DD];
__device__ __half g_qh [(size_t)BB * SS * DD];       // q fp16
__device__ __half g_kh [(size_t)BB * SS * DD];       // k fp16
__device__ __half g_vh [(size_t)BB * SS * DD];       // v fp16
__device__ __half g_vt [(size_t)BB * DD * SS];       // v^T fp16 [b][1024][2048]
__device__ float  g_s  [(size_t)BB * SS * SS];       // raw scores fp32
__device__ __half g_ah [(size_t)BB * SS * SS];       // attn fp16 [b][2048][2048]

// ---------------------------------------------------------------------------
// PTX helpers (compute_103-safe: cp.async, ldmatrix, mma.sync only)
// ---------------------------------------------------------------------------
__device__ __forceinline__ void cp16(uint32_t dst, const void* src) {
    asm volatile("cp.async.cg.shared.global [%0], [%1], 16;\n" :: "r"(dst), "l"(src));
}
__device__ __forceinline__ uint32_t swz128(uint32_t off) { return off ^ ((off >> 3) & 0x70); }

__device__ __forceinline__ void ldsm4(uint32_t& r0, uint32_t& r1, uint32_t& r2, uint32_t& r3,
                                      uint32_t addr) {
    asm volatile("ldmatrix.sync.aligned.m8n8.x4.shared.b16 {%0,%1,%2,%3}, [%4];"
                 : "=r"(r0), "=r"(r1), "=r"(r2), "=r"(r3) : "r"(addr));
}

__device__ __forceinline__ void mma_f16(float c[4], const uint32_t a[4], const uint32_t b0,
                                        const uint32_t b1) {
    asm volatile(
        "mma.sync.aligned.m16n8k16.row.col.f32.f16.f16.f32 "
        "{%0,%1,%2,%3}, {%4,%5,%6,%7}, {%8,%9}, {%0,%1,%2,%3};\n"
        : "+f"(c[0]), "+f"(c[1]), "+f"(c[2]), "+f"(c[3])
        : "r"(a[0]), "r"(a[1]), "r"(a[2]), "r"(a[3]), "r"(b0), "r"(b1));
}

// ---------------------------------------------------------------------------
// 1-pass fp16 GEMM: C[m][n] = sum_k A[m][k] * B[n][k], fp32 accumulate.
// CTA tile 128x128, chunk = 64 k per barrier (A 16KB + B 16KB, swz128 rows),
// 3-stage cp.async, 128 threads = 4 warps of 64x64, ldmatrix.x4 fragments.
// sched 1: fused QKV — A=x; B = Wq^T/Wk^T/Wv^T (w=t>>9); C fp16 (q/k/v)
// sched 2: scores QK^T — triangular causal list (136/batch); C fp32
// sched 3: attn @ V — K clamped at diagonal block, longest-first; C fp32
// ---------------------------------------------------------------------------
#define STAGE1 32768
#define GEMM_SMEM (3 * STAGE1)       // 98304

__global__ __launch_bounds__(128, 2)
void gemm1p(int sched,
            const __half* __restrict__ A,
            const __half* __restrict__ B0,
            const __half* __restrict__ B1,
            const __half* __restrict__ B2,
            void* __restrict__ C0, void* __restrict__ C1, void* __restrict__ C2)
{
    extern __shared__ __align__(1024) char smem[];
    const uint32_t base0 = (uint32_t)__cvta_generic_to_shared(smem);

    const int tid  = threadIdx.x;
    const int wid  = tid >> 5;
    const int lane = tid & 31;
    const int wm   = wid >> 1;      // 0..1
    const int wn   = wid & 1;       // 0..1

    // ---- decode tile ----
    const int t = blockIdx.x;
    const __half *Ag, *Bg;
    void* Cv;
    int m0, n0, N_C, rowA, rowB, nC, mode;
    if (sched == 1) {                       // fused QKV
        const int w = t >> 9;
        const int r = t & 511;
        m0 = (r >> 3) * 128; n0 = (r & 7) * 128;
        Ag = A;
        Bg = (w == 0) ? B0 : ((w == 1) ? B1 : B2);
        Cv = (w == 0) ? C0 : ((w == 1) ? C1 : C2);
        mode = 1;
        N_C = DD; rowA = DD; rowB = DD; nC = DD / 64;
    } else if (sched == 2) {                // scores, triangular decode
        const int z  = t / 136;
        const int tt = t - z * 136;
        int r = (int)floorf((sqrtf(8.0f * tt + 1.0f) - 1.0f) * 0.5f);
        while ((r + 1) * (r + 2) / 2 <= tt) r++;
        while (r * (r + 1) / 2 > tt) r--;
        const int c = tt - r * (r + 1) / 2;
        m0 = r * 128; n0 = c * 128;
        Ag = A  + (size_t)z * SS * DD;
        Bg = B0 + (size_t)z * SS * DD;
        Cv = (float*)C0 + (size_t)z * SS * SS;
        mode = 0; N_C = SS; rowA = DD; rowB = DD; nC = DD / 64;
    } else {                                // attn @ V, longest-first
        const int m    = 15 - (t >> 5);
        const int rest = t & 31;
        m0 = m * 128; n0 = (rest & 7) * 128;
        const int z = rest >> 3;
        Ag = A  + (size_t)z * SS * SS;
        Bg = B0 + (size_t)z * DD * SS;
        Cv = (float*)C0 + (size_t)z * SS * DD;
        mode = 0; N_C = DD; rowA = SS; rowB = SS;
        nC = min(SS / 64, 2 * m + 2);
    }

    // ldmatrix base offsets (rows of 128B = 64 k-cols, SW128 swizzle per use)
    const int mo  = ((lane >> 3) & 1) * 8 + (lane & 7);
    const int akb = ((lane >> 4) & 1) * 16;
    const int no  = ((lane >> 4) & 1) * 8 + (lane & 7);
    const int bkb = ((lane >> 3) & 1) * 16;
    uint32_t aO[4], bO[4];
    #pragma unroll
    for (int f = 0; f < 4; f++) {
        aO[f] = (uint32_t)((wm * 64 + f * 16 + mo) * 128 + akb);
        bO[f] = (uint32_t)((wn * 64 + f * 16 + no) * 128 + bkb);
    }

    float acc[4][8][4];
    #pragma unroll
    for (int i = 0; i < 4; i++)
        #pragma unroll
        for (int j = 0; j < 8; j++)
            #pragma unroll
            for (int q = 0; q < 4; q++) acc[i][j][q] = 0.0f;

    // chunk loader: thread t loads A row m0+t and B row n0+t (128B = 64 k each)
    auto load_chunk = [&](int c) {
        const int st = c % 3;
        const uint32_t aBase = base0 + st * STAGE1;
        const uint32_t bBase = aBase + 16384;
        const __half* as = Ag + (size_t)(m0 + tid) * rowA + c * 64;
        const __half* bs = Bg + (size_t)(n0 + tid) * rowB + c * 64;
        const uint32_t ro = (uint32_t)tid * 128;
        #pragma unroll
        for (int s8 = 0; s8 < 8; s8++) {
            cp16(aBase + swz128(ro + s8 * 16), as + s8 * 8);
            cp16(bBase + swz128(ro + s8 * 16), bs + s8 * 8);
        }
        asm volatile("cp.async.commit_group;\n");
    };

    load_chunk(0);
    if (nC > 1) load_chunk(1);

    for (int c = 0; c < nC; ++c) {
        if (c + 1 < nC) asm volatile("cp.async.wait_group 1;\n" ::: "memory");
        else            asm volatile("cp.async.wait_group 0;\n" ::: "memory");
        __syncthreads();

        if (c + 2 < nC) load_chunk(c + 2);

        const uint32_t aB = base0 + (c % 3) * STAGE1;
        const uint32_t bB = aB + 16384;

        #pragma unroll
        for (int ks = 0; ks < 4; ks++) {
            const uint32_t kso = (uint32_t)(ks * 32);
            uint32_t af[4][4], bf[4][4];
            #pragma unroll
            for (int f = 0; f < 4; f++)
                ldsm4(af[f][0], af[f][1], af[f][2], af[f][3], aB + swz128(aO[f] + kso));
            #pragma unroll
            for (int f = 0; f < 4; f++)
                ldsm4(bf[f][0], bf[f][1], bf[f][2], bf[f][3], bB + swz128(bO[f] + kso));
            #pragma unroll
            for (int im = 0; im < 4; im++)
                #pragma unroll
                for (int jn = 0; jn < 8; jn++)
                    mma_f16(acc[im][jn], af[im],
                            bf[jn >> 1][(jn & 1) * 2], bf[jn >> 1][(jn & 1) * 2 + 1]);
        }
    }

    // ---- epilogue ----
    #pragma unroll
    for (int im = 0; im < 4; im++) {
        const int r = m0 + wm * 64 + im * 16 + (lane >> 2);
        #pragma unroll
        for (int jn = 0; jn < 8; jn++) {
            const int cc = n0 + wn * 64 + jn * 8 + (lane & 3) * 2;
            if (mode == 0) {
                float* Cg = (float*)Cv;
                *(float2*)(Cg + (size_t)r * N_C + cc)       = make_float2(acc[im][jn][0], acc[im][jn][1]);
                *(float2*)(Cg + (size_t)(r + 8) * N_C + cc) = make_float2(acc[im][jn][2], acc[im][jn][3]);
            } else {
                __half* Cg = (__half*)Cv;
                #pragma unroll
                for (int hr = 0; hr < 2; hr++) {
                    const __half h0 = __float2half(acc[im][jn][hr * 2]);
                    const __half h1 = __float2half(acc[im][jn][hr * 2 + 1]);
                    *(__half2*)(Cg + (size_t)(r + hr * 8) * N_C + cc) = __halves2half2(h0, h1);
                }
            }
        }
    }
}

// ---------------------------------------------------------------------------
// fp32 -> fp16 convert (x)
// ---------------------------------------------------------------------------
__global__ __launch_bounds__(256)
void conv_h(const float* __restrict__ src, __half* __restrict__ dst)
{
    const long long idx = (long long)blockIdx.x * 256 + threadIdx.x;
    dst[idx] = __float2half(src[idx]);
}

// ---------------------------------------------------------------------------
// Merged weight transpose: fp32 [D][D] -> fp16 [D][D], 3 weights via z.
// ---------------------------------------------------------------------------
__global__ __launch_bounds__(256)
void transposeW(const float* __restrict__ s0, const float* __restrict__ s1,
                const float* __restrict__ s2,
                __half* __restrict__ d0, __half* __restrict__ d1,
                __half* __restrict__ d2)
{
    __shared__ float tile[32][33];
    const int z = blockIdx.z;
    const float* src = (z == 0) ? s0 : ((z == 1) ? s1 : s2);
    __half*      dst = (z == 0) ? d0 : ((z == 1) ? d1 : d2);
    const int r0 = blockIdx.y * 32, c0 = blockIdx.x * 32;
    const int tx = threadIdx.x & 31;
    const int ty = threadIdx.x >> 5;

    #pragma unroll
    for (int dy = 0; dy < 32; dy += 8)
        tile[ty + dy][tx] = src[(size_t)(r0 + ty + dy) * DD + c0 + tx];
    __syncthreads();

    #pragma unroll
    for (int dy = 0; dy < 32; dy += 8) {
        const int c = c0 + ty + dy;
        const int r = r0 + tx;
        dst[(size_t)c * DD + r] = __float2half(tile[tx][ty + dy]);
    }
}

// ---------------------------------------------------------------------------
// v transpose: fp16 [S][D] per batch -> fp16 [D][S]
// ---------------------------------------------------------------------------
__global__ __launch_bounds__(256)
void transposeV(const __half* __restrict__ src, __half* __restrict__ dst)
{
    __shared__ __half tile[32][40];
    src += (size_t)blockIdx.z * SS * DD;
    dst += (size_t)blockIdx.z * DD * SS;
    const int r0 = blockIdx.y * 32, c0 = blockIdx.x * 32;
    const int tx = threadIdx.x & 31;
    const int ty = threadIdx.x >> 5;

    #pragma unroll
    for (int dy = 0; dy < 32; dy += 8)
        tile[ty + dy][tx] = src[(size_t)(r0 + ty + dy) * DD + c0 + tx];
    __syncthreads();

    #pragma unroll
    for (int dy = 0; dy < 32; dy += 8) {
        const int c = c0 + ty + dy;
        const int r = r0 + tx;
        dst[(size_t)c * SS + r] = tile[tx][ty + dy];
    }
}

// ---------------------------------------------------------------------------
// Causal softmax emitting fp16 attn. Zero-fills only up to the 128-row
// diagonal-block boundary (AV K-clamp never reads past it).
// ---------------------------------------------------------------------------
__global__ __launch_bounds__(256)
void softmax1(const float* __restrict__ Sc, __half* __restrict__ Ah,
              int S, float scale)
{
    const long long row = blockIdx.x;            // b*S + i
    const int i = (int)(row % S);
    const float* p = Sc + row * (long long)S;
    __half* out = Ah + row * (long long)S;
    const int L = i + 1;
    const int Lz = ((i >> 7) + 1) << 7;          // diagonal-block end

    const int tid  = threadIdx.x;
    const int lane = tid & 31;
    const int wid  = tid >> 5;
    __shared__ float red[32];

    float mx = -INFINITY;
    for (int j = tid; j < L; j += 256) mx = fmaxf(mx, p[j]);
    #pragma unroll
    for (int o = 16; o; o >>= 1) mx = fmaxf(mx, __shfl_xor_sync(0xffffffffu, mx, o));
    if (lane == 0) red[wid] = mx;
    __syncthreads();
    if (tid == 0) {
        float m = red[0];
        #pragma unroll
        for (int w = 1; w < 8; w++) m = fmaxf(m, red[w]);
        red[0] = m;
    }
    __syncthreads();
    mx = red[0];
    __syncthreads();

    float e[8];
    float sum = 0.0f;
    int cnt = 0;
    for (int j = tid; j < L; j += 256) {
        const float ev = __expf((p[j] - mx) * scale);
        e[cnt++] = ev;
        sum += ev;
    }
    #pragma unroll
    for (int o = 16; o; o >>= 1) sum += __shfl_xor_sync(0xffffffffu, sum, o);
    if (lane == 0) red[wid] = sum;
    __syncthreads();
    if (tid == 0) {
        float s = red[0];
        #pragma unroll
        for (int w = 1; w < 8; w++) s += red[w];
        red[0] = s;
    }
    __syncthreads();
    const float inv = 1.0f / red[0];

    cnt = 0;
    for (int j = tid; j < L; j += 256)
        out[j] = __float2half(e[cnt++] * inv);
    const __half zero = __float2half(0.0f);
    for (int j = L + tid; j < Lz; j += 256)
        out[j] = zero;
}

// ---------------------------------------------------------------------------
extern "C" void kernel_launch(void* const* d_in, const int* in_sizes, int n_in,
                              void* d_out, int out_size)
{
    (void)in_sizes; (void)n_in; (void)out_size;
    const float* x  = (const float*)d_in[0];
    const float* Wq = (const float*)d_in[1];
    const float* Wk = (const float*)d_in[2];
    const float* Wv = (const float*)d_in[3];
    float* out = (float*)d_out;

    __half *xh, *wqt, *wkt, *wvt, *qh, *kh, *vh, *vt, *ah;
    float *s;
    cudaGetSymbolAddress((void**)&xh,  g_xh);
    cudaGetSymbolAddress((void**)&wqt, g_wqt);
    cudaGetSymbolAddress((void**)&wkt, g_wkt);
    cudaGetSymbolAddress((void**)&wvt, g_wvt);
    cudaGetSymbolAddress((void**)&qh,  g_qh);
    cudaGetSymbolAddress((void**)&kh,  g_kh);
    cudaGetSymbolAddress((void**)&vh,  g_vh);
    cudaGetSymbolAddress((void**)&vt,  g_vt);
    cudaGetSymbolAddress((void**)&s,   g_s);
    cudaGetSymbolAddress((void**)&ah,  g_ah);

    cudaFuncSetAttribute(gemm1p, cudaFuncAttributeMaxDynamicSharedMemorySize, GEMM_SMEM);

    const int B = BB, S = SS, D = DD;
    const long long MS = (long long)B * S;   // 8192

    // launch 0: x -> fp16
    conv_h<<<(int)(MS * D / 256), 256>>>(x, xh);

    // launch 1: merged weight transposes -> fp16
    {
        dim3 tg(D / 32, D / 32, 3);
        transposeW<<<tg, 256>>>(Wq, Wk, Wv, wqt, wkt, wvt);
    }

    // launch 2: fused QKV (1536 tiles) -> q/k/v fp16
    gemm1p<<<1536, 128, GEMM_SMEM>>>(1, xh, wqt, wkt, wvt, qh, kh, vh);

    // launch 3 (ncu-captured): scores = Q K^T, triangular tile list
    gemm1p<<<136 * B, 128, GEMM_SMEM>>>(2, qh, kh, nullptr, nullptr,
                                        s, nullptr, nullptr);

    // launch 4: v transpose (fp16 -> fp16)
    {
        dim3 tg(D / 32, S / 32, B);
        transposeV<<<tg, 256>>>(vh, vt);
    }

    // launch 5: softmax -> fp16 attn
    softmax1<<<B * S, 256>>>(s, ah, S, 0.03125f);

    // launch 6: out = attn @ V (K-clamped, longest tiles first)
    gemm1p<<<16 * 8 * B, 128, GEMM_SMEM>>>(3, ah, vt, nullptr, nullptr,
                                           out, nullptr, nullptr);
}

// round 13
// speedup vs baseline: 2.3582x; 1.0332x over previous
#include <cuda_runtime.h>
#include <cuda_fp16.h>
#include <cstdint>
#include <math.h>

#define BB 4
#define SS 2048
#define DD 1024

// ---------------------------------------------------------------------------
// Scratch (device globals — allocation-free per harness rules)
// All operands plain fp16 (1-pass scheme); fp32 accumulate in MMA.
// Calibrated error model: ~10 incoherent fp16-round components -> ~5.9e-4.
// ---------------------------------------------------------------------------
__device__ __half g_xh [(size_t)BB * SS * DD];       // x fp16    [8192][1024]
__device__ __half g_wqt[(size_t)DD * DD];            // Wq^T fp16 [1024][1024]
__device__ __half g_wkt[(size_t)DD * DD];
__device__ __half g_wvt[(size_t)DD * DD];
__device__ __half g_qh [(size_t)BB * SS * DD];       // q fp16
__device__ __half g_kh [(size_t)BB * SS * DD];       // k fp16
__device__ __half g_vh [(size_t)BB * SS * DD];       // v fp16
__device__ __half g_vt [(size_t)BB * DD * SS];       // v^T fp16 [b][1024][2048]
__device__ float  g_s  [(size_t)BB * SS * SS];       // raw scores fp32
__device__ __half g_ah [(size_t)BB * SS * SS];       // attn fp16 [b][2048][2048]

// ---------------------------------------------------------------------------
// PTX helpers (compute_103-safe: cp.async, ldmatrix, mma.sync only)
// ---------------------------------------------------------------------------
__device__ __forceinline__ void cp16(uint32_t dst, const void* src) {
    asm volatile("cp.async.cg.shared.global [%0], [%1], 16;\n" :: "r"(dst), "l"(src));
}
__device__ __forceinline__ uint32_t swz128(uint32_t off) { return off ^ ((off >> 3) & 0x70); }

__device__ __forceinline__ void ldsm4(uint32_t& r0, uint32_t& r1, uint32_t& r2, uint32_t& r3,
                                      uint32_t addr) {
    asm volatile("ldmatrix.sync.aligned.m8n8.x4.shared.b16 {%0,%1,%2,%3}, [%4];"
                 : "=r"(r0), "=r"(r1), "=r"(r2), "=r"(r3) : "r"(addr));
}

__device__ __forceinline__ void mma_f16(float c[4], const uint32_t a[4], const uint32_t b0,
                                        const uint32_t b1) {
    asm volatile(
        "mma.sync.aligned.m16n8k16.row.col.f32.f16.f16.f32 "
        "{%0,%1,%2,%3}, {%4,%5,%6,%7}, {%8,%9}, {%0,%1,%2,%3};\n"
        : "+f"(c[0]), "+f"(c[1]), "+f"(c[2]), "+f"(c[3])
        : "r"(a[0]), "r"(a[1]), "r"(a[2]), "r"(a[3]), "r"(b0), "r"(b1));
}

// ---------------------------------------------------------------------------
// 1-pass fp16 GEMM: C[m][n] = sum_k A[m][k] * B[n][k], fp32 accumulate.
// CTA tile 128x128, chunk = 64 k per barrier (A 16KB + B 16KB, swz128 rows),
// 3-stage cp.async, 128 threads = 4 warps of 64x64, ldmatrix.x4 fragments
// with explicit register double-buffering across the 4 ks sub-steps.
// sched 1: fused QKV — A=x; B = Wq^T/Wk^T/Wv^T (w=t>>9); C fp16 (q/k/v)
// sched 2: scores QK^T — triangular causal list (136/batch); C fp32
// sched 3: attn @ V — K clamped at diagonal block, longest-first; C fp32
// ---------------------------------------------------------------------------
#define STAGE1 32768
#define GEMM_SMEM (3 * STAGE1)       // 98304

__global__ __launch_bounds__(128, 2)
void gemm1p(int sched,
            const __half* __restrict__ A,
            const __half* __restrict__ B0,
            const __half* __restrict__ B1,
            const __half* __restrict__ B2,
            void* __restrict__ C0, void* __restrict__ C1, void* __restrict__ C2)
{
    extern __shared__ __align__(1024) char smem[];
    const uint32_t base0 = (uint32_t)__cvta_generic_to_shared(smem);

    const int tid  = threadIdx.x;
    const int wid  = tid >> 5;
    const int lane = tid & 31;
    const int wm   = wid >> 1;      // 0..1
    const int wn   = wid & 1;       // 0..1

    // ---- decode tile ----
    const int t = blockIdx.x;
    const __half *Ag, *Bg;
    void* Cv;
    int m0, n0, N_C, rowA, rowB, nC, mode;
    if (sched == 1) {                       // fused QKV
        const int w = t >> 9;
        const int r = t & 511;
        m0 = (r >> 3) * 128; n0 = (r & 7) * 128;
        Ag = A;
        Bg = (w == 0) ? B0 : ((w == 1) ? B1 : B2);
        Cv = (w == 0) ? C0 : ((w == 1) ? C1 : C2);
        mode = 1;
        N_C = DD; rowA = DD; rowB = DD; nC = DD / 64;
    } else if (sched == 2) {                // scores, triangular decode
        const int z  = t / 136;
        const int tt = t - z * 136;
        int r = (int)floorf((sqrtf(8.0f * tt + 1.0f) - 1.0f) * 0.5f);
        while ((r + 1) * (r + 2) / 2 <= tt) r++;
        while (r * (r + 1) / 2 > tt) r--;
        const int c = tt - r * (r + 1) / 2;
        m0 = r * 128; n0 = c * 128;
        Ag = A  + (size_t)z * SS * DD;
        Bg = B0 + (size_t)z * SS * DD;
        Cv = (float*)C0 + (size_t)z * SS * SS;
        mode = 0; N_C = SS; rowA = DD; rowB = DD; nC = DD / 64;
    } else {                                // attn @ V, longest-first
        const int m    = 15 - (t >> 5);
        const int rest = t & 31;
        m0 = m * 128; n0 = (rest & 7) * 128;
        const int z = rest >> 3;
        Ag = A  + (size_t)z * SS * SS;
        Bg = B0 + (size_t)z * DD * SS;
        Cv = (float*)C0 + (size_t)z * SS * DD;
        mode = 0; N_C = DD; rowA = SS; rowB = SS;
        nC = min(SS / 64, 2 * m + 2);
    }

    // ldmatrix base offsets (rows of 128B = 64 k-cols, SW128 swizzle per use)
    const int mo  = ((lane >> 3) & 1) * 8 + (lane & 7);
    const int akb = ((lane >> 4) & 1) * 16;
    const int no  = ((lane >> 4) & 1) * 8 + (lane & 7);
    const int bkb = ((lane >> 3) & 1) * 16;
    uint32_t aO[4], bO[4];
    #pragma unroll
    for (int f = 0; f < 4; f++) {
        aO[f] = (uint32_t)((wm * 64 + f * 16 + mo) * 128 + akb);
        bO[f] = (uint32_t)((wn * 64 + f * 16 + no) * 128 + bkb);
    }

    float acc[4][8][4];
    #pragma unroll
    for (int i = 0; i < 4; i++)
        #pragma unroll
        for (int j = 0; j < 8; j++)
            #pragma unroll
            for (int q = 0; q < 4; q++) acc[i][j][q] = 0.0f;

    // chunk loader: thread t loads A row m0+t and B row n0+t (128B = 64 k each)
    auto load_chunk = [&](int c) {
        const int st = c % 3;
        const uint32_t aBase = base0 + st * STAGE1;
        const uint32_t bBase = aBase + 16384;
        const __half* as = Ag + (size_t)(m0 + tid) * rowA + c * 64;
        const __half* bs = Bg + (size_t)(n0 + tid) * rowB + c * 64;
        const uint32_t ro = (uint32_t)tid * 128;
        #pragma unroll
        for (int s8 = 0; s8 < 8; s8++) {
            cp16(aBase + swz128(ro + s8 * 16), as + s8 * 8);
            cp16(bBase + swz128(ro + s8 * 16), bs + s8 * 8);
        }
        asm volatile("cp.async.commit_group;\n");
    };

    load_chunk(0);
    if (nC > 1) load_chunk(1);

    uint32_t af[2][4][4], bf[2][4][4];

    for (int c = 0; c < nC; ++c) {
        if (c + 1 < nC) asm volatile("cp.async.wait_group 1;\n" ::: "memory");
        else            asm volatile("cp.async.wait_group 0;\n" ::: "memory");
        __syncthreads();

        if (c + 2 < nC) load_chunk(c + 2);

        const uint32_t aB = base0 + (c % 3) * STAGE1;
        const uint32_t bB = aB + 16384;

        // prime ks=0 fragments
        #pragma unroll
        for (int f = 0; f < 4; f++)
            ldsm4(af[0][f][0], af[0][f][1], af[0][f][2], af[0][f][3],
                  aB + swz128(aO[f]));
        #pragma unroll
        for (int f = 0; f < 4; f++)
            ldsm4(bf[0][f][0], bf[0][f][1], bf[0][f][2], bf[0][f][3],
                  bB + swz128(bO[f]));

        #pragma unroll
        for (int ks = 0; ks < 4; ks++) {
            const int p = ks & 1;
            if (ks < 3) {               // prefetch ks+1 while issuing ks MMAs
                const int q = 1 - p;
                const uint32_t kso = (uint32_t)((ks + 1) * 32);
                #pragma unroll
                for (int f = 0; f < 4; f++)
                    ldsm4(af[q][f][0], af[q][f][1], af[q][f][2], af[q][f][3],
                          aB + swz128(aO[f] + kso));
                #pragma unroll
                for (int f = 0; f < 4; f++)
                    ldsm4(bf[q][f][0], bf[q][f][1], bf[q][f][2], bf[q][f][3],
                          bB + swz128(bO[f] + kso));
            }
            #pragma unroll
            for (int im = 0; im < 4; im++)
                #pragma unroll
                for (int jn = 0; jn < 8; jn++)
                    mma_f16(acc[im][jn], af[p][im],
                            bf[p][jn >> 1][(jn & 1) * 2], bf[p][jn >> 1][(jn & 1) * 2 + 1]);
        }
    }

    // ---- epilogue ----
    #pragma unroll
    for (int im = 0; im < 4; im++) {
        const int r = m0 + wm * 64 + im * 16 + (lane >> 2);
        #pragma unroll
        for (int jn = 0; jn < 8; jn++) {
            const int cc = n0 + wn * 64 + jn * 8 + (lane & 3) * 2;
            if (mode == 0) {
                float* Cg = (float*)Cv;
                *(float2*)(Cg + (size_t)r * N_C + cc)       = make_float2(acc[im][jn][0], acc[im][jn][1]);
                *(float2*)(Cg + (size_t)(r + 8) * N_C + cc) = make_float2(acc[im][jn][2], acc[im][jn][3]);
            } else {
                __half* Cg = (__half*)Cv;
                #pragma unroll
                for (int hr = 0; hr < 2; hr++) {
                    const __half h0 = __float2half(acc[im][jn][hr * 2]);
                    const __half h1 = __float2half(acc[im][jn][hr * 2 + 1]);
                    *(__half2*)(Cg + (size_t)(r + hr * 8) * N_C + cc) = __halves2half2(h0, h1);
                }
            }
        }
    }
}

// ---------------------------------------------------------------------------
// fp32 -> fp16 convert (x), 4 elements per thread
// ---------------------------------------------------------------------------
__global__ __launch_bounds__(256)
void conv_h(const float* __restrict__ src, __half* __restrict__ dst)
{
    const long long idx = ((long long)blockIdx.x * 256 + threadIdx.x) * 4;
    const float4 v = *(const float4*)(src + idx);
    __half2* o = (__half2*)(dst + idx);
    o[0] = __halves2half2(__float2half(v.x), __float2half(v.y));
    o[1] = __halves2half2(__float2half(v.z), __float2half(v.w));
}

// ---------------------------------------------------------------------------
// Merged weight transpose: fp32 [D][D] -> fp16 [D][D], 3 weights via z.
// ---------------------------------------------------------------------------
__global__ __launch_bounds__(256)
void transposeW(const float* __restrict__ s0, const float* __restrict__ s1,
                const float* __restrict__ s2,
                __half* __restrict__ d0, __half* __restrict__ d1,
                __half* __restrict__ d2)
{
    __shared__ float tile[32][33];
    const int z = blockIdx.z;
    const float* src = (z == 0) ? s0 : ((z == 1) ? s1 : s2);
    __half*      dst = (z == 0) ? d0 : ((z == 1) ? d1 : d2);
    const int r0 = blockIdx.y * 32, c0 = blockIdx.x * 32;
    const int tx = threadIdx.x & 31;
    const int ty = threadIdx.x >> 5;

    #pragma unroll
    for (int dy = 0; dy < 32; dy += 8)
        tile[ty + dy][tx] = src[(size_t)(r0 + ty + dy) * DD + c0 + tx];
    __syncthreads();

    #pragma unroll
    for (int dy = 0; dy < 32; dy += 8) {
        const int c = c0 + ty + dy;
        const int r = r0 + tx;
        dst[(size_t)c * DD + r] = __float2half(tile[tx][ty + dy]);
    }
}

// ---------------------------------------------------------------------------
// v transpose: fp16 [S][D] per batch -> fp16 [D][S]
// ---------------------------------------------------------------------------
__global__ __launch_bounds__(256)
void transposeV(const __half* __restrict__ src, __half* __restrict__ dst)
{
    __shared__ __half tile[32][40];
    src += (size_t)blockIdx.z * SS * DD;
    dst += (size_t)blockIdx.z * DD * SS;
    const int r0 = blockIdx.y * 32, c0 = blockIdx.x * 32;
    const int tx = threadIdx.x & 31;
    const int ty = threadIdx.x >> 5;

    #pragma unroll
    for (int dy = 0; dy < 32; dy += 8)
        tile[ty + dy][tx] = src[(size_t)(r0 + ty + dy) * DD + c0 + tx];
    __syncthreads();

    #pragma unroll
    for (int dy = 0; dy < 32; dy += 8) {
        const int c = c0 + ty + dy;
        const int r = r0 + tx;
        dst[(size_t)c * SS + r] = tile[tx][ty + dy];
    }
}

// ---------------------------------------------------------------------------
// Vectorized causal softmax -> fp16 attn. Processes the whole [0, Lz) range
// 4-wide with arithmetic masking (j > i -> -inf -> e = 0), so masked lanes
// come out as exact zeros and no scalar tail loops are needed.
// Lz = diagonal-block end (multiple of 128); AV K-clamp never reads past it.
// ---------------------------------------------------------------------------
__global__ __launch_bounds__(256)
void softmax1(const float* __restrict__ Sc, __half* __restrict__ Ah,
              int S, float scale)
{
    const long long row = blockIdx.x;            // b*S + i
    const int i = (int)(row % S);
    const float* p = Sc + row * (long long)S;
    __half* out = Ah + row * (long long)S;
    const int Lz = ((i >> 7) + 1) << 7;          // multiple of 128

    const int tid  = threadIdx.x;
    const int lane = tid & 31;
    const int wid  = tid >> 5;
    __shared__ float red[32];

    // ---- pass 1: masked max ----
    float mx = -INFINITY;
    for (int j = tid * 4; j < Lz; j += 1024) {
        float4 v = *(const float4*)(p + j);
        if (j + 0 > i) v.x = -INFINITY;
        if (j + 1 > i) v.y = -INFINITY;
        if (j + 2 > i) v.z = -INFINITY;
        if (j + 3 > i) v.w = -INFINITY;
        mx = fmaxf(mx, fmaxf(fmaxf(v.x, v.y), fmaxf(v.z, v.w)));
    }
    #pragma unroll
    for (int o = 16; o; o >>= 1) mx = fmaxf(mx, __shfl_xor_sync(0xffffffffu, mx, o));
    if (lane == 0) red[wid] = mx;
    __syncthreads();
    if (tid == 0) {
        float m = red[0];
        #pragma unroll
        for (int w = 1; w < 8; w++) m = fmaxf(m, red[w]);
        red[0] = m;
    }
    __syncthreads();
    mx = red[0];
    __syncthreads();

    // ---- pass 2: masked exp + sum (register-cached) ----
    float e[8];
    float sum = 0.0f;
    int cnt = 0;
    for (int j = tid * 4; j < Lz; j += 1024) {
        float4 v = *(const float4*)(p + j);
        const float e0 = (j + 0 <= i) ? __expf((v.x - mx) * scale) : 0.0f;
        const float e1 = (j + 1 <= i) ? __expf((v.y - mx) * scale) : 0.0f;
        const float e2 = (j + 2 <= i) ? __expf((v.z - mx) * scale) : 0.0f;
        const float e3 = (j + 3 <= i) ? __expf((v.w - mx) * scale) : 0.0f;
        e[cnt + 0] = e0; e[cnt + 1] = e1; e[cnt + 2] = e2; e[cnt + 3] = e3;
        cnt += 4;
        sum += (e0 + e1) + (e2 + e3);
    }
    #pragma unroll
    for (int o = 16; o; o >>= 1) sum += __shfl_xor_sync(0xffffffffu, sum, o);
    if (lane == 0) red[wid] = sum;
    __syncthreads();
    if (tid == 0) {
        float s = red[0];
        #pragma unroll
        for (int w = 1; w < 8; w++) s += red[w];
        red[0] = s;
    }
    __syncthreads();
    const float inv = 1.0f / red[0];

    // ---- pass 3: normalize + fp16 store (masked lanes are exact zeros) ----
    cnt = 0;
    for (int j = tid * 4; j < Lz; j += 1024) {
        __half2* o2 = (__half2*)(out + j);
        o2[0] = __halves2half2(__float2half(e[cnt + 0] * inv),
                               __float2half(e[cnt + 1] * inv));
        o2[1] = __halves2half2(__float2half(e[cnt + 2] * inv),
                               __float2half(e[cnt + 3] * inv));
        cnt += 4;
    }
}

// ---------------------------------------------------------------------------
extern "C" void kernel_launch(void* const* d_in, const int* in_sizes, int n_in,
                              void* d_out, int out_size)
{
    (void)in_sizes; (void)n_in; (void)out_size;
    const float* x  = (const float*)d_in[0];
    const float* Wq = (const float*)d_in[1];
    const float* Wk = (const float*)d_in[2];
    const float* Wv = (const float*)d_in[3];
    float* out = (float*)d_out;

    __half *xh, *wqt, *wkt, *wvt, *qh, *kh, *vh, *vt, *ah;
    float *s;
    cudaGetSymbolAddress((void**)&xh,  g_xh);
    cudaGetSymbolAddress((void**)&wqt, g_wqt);
    cudaGetSymbolAddress((void**)&wkt, g_wkt);
    cudaGetSymbolAddress((void**)&wvt, g_wvt);
    cudaGetSymbolAddress((void**)&qh,  g_qh);
    cudaGetSymbolAddress((void**)&kh,  g_kh);
    cudaGetSymbolAddress((void**)&vh,  g_vh);
    cudaGetSymbolAddress((void**)&vt,  g_vt);
    cudaGetSymbolAddress((void**)&s,   g_s);
    cudaGetSymbolAddress((void**)&ah,  g_ah);

    cudaFuncSetAttribute(gemm1p, cudaFuncAttributeMaxDynamicSharedMemorySize, GEMM_SMEM);

    const int B = BB, S = SS, D = DD;
    const long long MS = (long long)B * S;   // 8192

    // launch 0: x -> fp16 (4-wide)
    conv_h<<<(int)(MS * D / 1024), 256>>>(x, xh);

    // launch 1: merged weight transposes -> fp16
    {
        dim3 tg(D / 32, D / 32, 3);
        transposeW<<<tg, 256>>>(Wq, Wk, Wv, wqt, wkt, wvt);
    }

    // launch 2: fused QKV (1536 tiles) -> q/k/v fp16
    gemm1p<<<1536, 128, GEMM_SMEM>>>(1, xh, wqt, wkt, wvt, qh, kh, vh);

    // launch 3 (ncu-captured): scores = Q K^T, triangular tile list
    gemm1p<<<136 * B, 128, GEMM_SMEM>>>(2, qh, kh, nullptr, nullptr,
                                        s, nullptr, nullptr);

    // launch 4: v transpose (fp16 -> fp16)
    {
        dim3 tg(D / 32, S / 32, B);
        transposeV<<<tg, 256>>>(vh, vt);
    }

    // launch 5: vectorized softmax -> fp16 attn
    softmax1<<<B * S, 256>>>(s, ah, S, 0.03125f);

    // launch 6: out = attn @ V (K-clamped, longest tiles first)
    gemm1p<<<16 * 8 * B, 128, GEMM_SMEM>>>(3, ah, vt, nullptr, nullptr,
                                           out, nullptr, nullptr);
}